// round 11
// baseline (speedup 1.0000x reference)
#include <cuda_runtime.h>
#include <cuda_fp16.h>
#include <cmath>
#include <cstdint>

#define Bq 16
#define Cq 256
#define Tq 128
#define Vq 64
#define Kq 8
#define Oq 256
#define TVq 8192
#define CNT 131072
#define NBLK 1024            // GEMM blocks per launch = 64 * 16

// ---------------- scratch ----------------
__device__ float  g_tp[Bq*Cq*Vq];
__device__ float  g_x1[Bq*Oq*Vq];
__device__ float  g_x2[Bq*Oq*Vq];
__device__ float  g_M [Bq*Kq*Vq*Vq];
__device__ float  g_stats[4*Oq];
__device__ float  g_psum[2][NBLK][Oq];         // deterministic BN partials
__device__ float  g_psq [2][NBLK][Oq];
__device__ __half g_xh  [(size_t)Bq*Cq*TVq];   // fp16 copy of x
__device__ __half g_bufAh[(size_t)Bq*Oq*TVq];  // stem out y / head out z (fp16)
__device__ __half g_bufBh[(size_t)Bq*Oq*TVq];  // stage5 out (fp16)
__device__ __half g_wh[2*Oq*Cq];               // fp16 stem_w, head_w

// ---------------- helpers ----------------
__device__ __forceinline__ void mma_f16(float c[4],
                                        uint32_t a0, uint32_t a1, uint32_t a2, uint32_t a3,
                                        uint32_t b0, uint32_t b1) {
    asm volatile(
        "mma.sync.aligned.m16n8k16.row.col.f32.f16.f16.f32 "
        "{%0,%1,%2,%3},{%4,%5,%6,%7},{%8,%9},{%0,%1,%2,%3};\n"
        : "+f"(c[0]), "+f"(c[1]), "+f"(c[2]), "+f"(c[3])
        : "r"(a0), "r"(a1), "r"(a2), "r"(a3), "r"(b0), "r"(b1));
}
__device__ __forceinline__ void ldsm_x4(uint32_t& r0, uint32_t& r1, uint32_t& r2, uint32_t& r3,
                                        uint32_t addr) {
    asm volatile("ldmatrix.sync.aligned.m8n8.x4.shared.b16 {%0,%1,%2,%3}, [%4];\n"
                 : "=r"(r0), "=r"(r1), "=r"(r2), "=r"(r3) : "r"(addr));
}
__device__ __forceinline__ void ldsm_x4_t(uint32_t& r0, uint32_t& r1, uint32_t& r2, uint32_t& r3,
                                          uint32_t addr) {
    asm volatile("ldmatrix.sync.aligned.m8n8.x4.trans.shared.b16 {%0,%1,%2,%3}, [%4];\n"
                 : "=r"(r0), "=r"(r1), "=r"(r2), "=r"(r3) : "r"(addr));
}
__device__ __forceinline__ void cpasync16(uint32_t saddr, const void* g) {
    asm volatile("cp.async.cg.shared.global [%0], [%1], 16;\n" :: "r"(saddr), "l"(g));
}
#define CP_COMMIT() asm volatile("cp.async.commit_group;\n" ::: "memory")
#define CP_WAIT(n)  asm volatile("cp.async.wait_group %0;\n" :: "n"(n) : "memory")

// x -> fp16 copy + per-(b,c) mean over T; extra blocks convert weights
__global__ void k_meanT(const float* __restrict__ x,
                        const float* __restrict__ sw, const float* __restrict__ hw) {
    int bc = blockIdx.x;
    int tid = threadIdx.x;
    if (bc >= Bq*Cq) {                    // weight-conversion blocks
        int i = (bc - Bq*Cq)*256 + tid;
        g_wh[i]         = __float2half(sw[i]);
        g_wh[Oq*Cq + i] = __float2half(hw[i]);
        return;
    }
    int lane = tid & 31, warp = tid >> 5;
    __shared__ float red[8][64];
    const float4* p = (const float4*)(x + (size_t)bc*TVq);
    __half* xo = g_xh + (size_t)bc*TVq;
    float s0=0.f, s1=0.f, s2=0.f, s3=0.f;
    int v0 = (tid*4) & 63;
    #pragma unroll
    for (int i = 0; i < 8; i++) {
        int e = tid + i*256;
        float4 f = p[e];
        s0 += f.x; s1 += f.y; s2 += f.z; s3 += f.w;
        ((__half2*)xo)[e*2]     = __floats2half2_rn(f.x, f.y);
        ((__half2*)xo)[e*2 + 1] = __floats2half2_rn(f.z, f.w);
    }
    s0 += __shfl_xor_sync(0xffffffffu, s0, 16);
    s1 += __shfl_xor_sync(0xffffffffu, s1, 16);
    s2 += __shfl_xor_sync(0xffffffffu, s2, 16);
    s3 += __shfl_xor_sync(0xffffffffu, s3, 16);
    if (lane < 16) {
        red[warp][v0]   = s0;
        red[warp][v0+1] = s1;
        red[warp][v0+2] = s2;
        red[warp][v0+3] = s3;
    }
    __syncthreads();
    if (tid < 64) {
        float s = 0.f;
        #pragma unroll
        for (int w = 0; w < 8; w++) s += red[w][tid];
        g_tp[bc*Vq + tid] = s * (1.f/Tq);
    }
}

// x1/x2 = conv1x1(tp) — tiled
__global__ void __launch_bounds__(256) k_x1x2(const float* __restrict__ w1, const float* __restrict__ b1,
                                              const float* __restrict__ w2, const float* __restrict__ b2) {
    __shared__ float tps[64][64];
    __shared__ float w1s[16][64];
    __shared__ float w2s[16][64];
    int b = blockIdx.y, ot = blockIdx.x * 16;
    int tid = threadIdx.x;
    int v = tid & 63, og = tid >> 6;
    float a1[4] = {0.f,0.f,0.f,0.f}, a2[4] = {0.f,0.f,0.f,0.f};

    for (int c0 = 0; c0 < Cq; c0 += 64) {
        __syncthreads();
        #pragma unroll
        for (int i = 0; i < 16; i++) {
            int idx = tid + i*256;
            tps[idx >> 6][idx & 63] = g_tp[(b*Cq + c0 + (idx >> 6))*Vq + (idx & 63)];
        }
        #pragma unroll
        for (int i = 0; i < 4; i++) {
            int idx = tid + i*256;
            int o = idx >> 6, cc = idx & 63;
            w1s[o][cc] = w1[(ot + o)*Cq + c0 + cc];
            w2s[o][cc] = w2[(ot + o)*Cq + c0 + cc];
        }
        __syncthreads();
        #pragma unroll 8
        for (int cc = 0; cc < 64; cc++) {
            float t = tps[cc][v];
            #pragma unroll
            for (int j = 0; j < 4; j++) {
                a1[j] = fmaf(t, w1s[og*4 + j][cc], a1[j]);
                a2[j] = fmaf(t, w2s[og*4 + j][cc], a2[j]);
            }
        }
    }
    #pragma unroll
    for (int j = 0; j < 4; j++) {
        int o = ot + og*4 + j;
        g_x1[(b*Oq + o)*Vq + v] = a1[j] + b1[o];
        g_x2[(b*Oq + o)*Vq + v] = a2[j] + b2[o];
    }
}

// M = A_param + beta * softmax
__global__ void k_adj(const float* __restrict__ Ap, const float* __restrict__ beta_p) {
    __shared__ float x1s[32][Vq];
    __shared__ float x2s[32][Vq];
    __shared__ float S[Vq][Vq];
    __shared__ float mred[4][64];
    __shared__ float sred2[4][64];
    int bk = blockIdx.x;
    int b = bk >> 3, k = bk & 7;
    int tid = threadIdx.x;

    for (int i = tid; i < 32*Vq; i += 256) {
        int c = i >> 6, v = i & 63;
        int row = (b*Oq + k*32 + c)*Vq + v;
        x1s[c][v] = g_x1[row];
        x2s[c][v] = g_x2[row];
    }
    __syncthreads();
    for (int i = tid; i < Vq*Vq; i += 256) {
        int v = i >> 6, w = i & 63;
        float s = 0.f;
        #pragma unroll
        for (int c = 0; c < 32; c++) s = fmaf(x1s[c][v], x2s[c][w], s);
        S[v][w] = s;
    }
    __syncthreads();

    int w = tid & 63, part = tid >> 6;
    int vlo = part*16;
    float m = -1e30f;
    #pragma unroll
    for (int v = 0; v < 16; v++) m = fmaxf(m, S[vlo + v][w]);
    mred[part][w] = m;
    __syncthreads();
    m = fmaxf(fmaxf(mred[0][w], mred[1][w]), fmaxf(mred[2][w], mred[3][w]));
    float sum = 0.f;
    #pragma unroll
    for (int v = 0; v < 16; v++) {
        float e = __expf(S[vlo + v][w] - m);
        S[vlo + v][w] = e;
        sum += e;
    }
    sred2[part][w] = sum;
    __syncthreads();
    float tot = sred2[0][w] + sred2[1][w] + sred2[2][w] + sred2[3][w];
    float scl = beta_p[0] / tot;
    #pragma unroll
    for (int v = 0; v < 16; v++) {
        int vv = vlo + v;
        g_M[((bk*Vq + vv) << 6) + w] = Ap[((k*Vq + vv) << 6) + w] + S[vv][w]*scl;
    }
}

// ---------------- fp16 GEMM: Y = W(256m) @ X(128n), k=256; 512 threads, 16 warps ----------------
#define WSPh 40
#define XSPh 136
#define WSTh (256*WSPh)           // 10240 halfs
#define XSTh (32*XSPh)            // 4352 halfs
#define GSTAGEh (WSTh + XSTh)     // 14592 halfs = 29184 B
#define NSTAGE 4

__global__ void __launch_bounds__(512, 1) k_gemm(const __half* __restrict__ Wh,
                                                 const __half* __restrict__ Xg,
                                                 int part) {
    extern __shared__ __align__(16) char smraw[];
    __half* smem = (__half*)smraw;
    __shared__ float sred[2][256][4];     // [stat][row][wn]
    int b  = blockIdx.z;
    int n0 = blockIdx.x * 128;
    int tid  = threadIdx.x;
    int warp = tid >> 5, lane = tid & 31;
    int wm = warp >> 2, wn = warp & 3;           // 4 x 4 warps, warp tile 64m x 32n
    int r  = lane >> 2, c = lane & 3;
    int l16 = lane & 15, lh = lane >> 4;

    const __half* Xb = Xg + (size_t)b*Cq*TVq;
    uint32_t sbase = (uint32_t)__cvta_generic_to_shared(smem);

    float acc[4][4][4];
    #pragma unroll
    for (int i = 0; i < 4; i++)
        #pragma unroll
        for (int j = 0; j < 4; j++)
            #pragma unroll
            for (int q = 0; q < 4; q++) acc[i][j][q] = 0.f;

    auto load_stage = [&](int kt, int s) {
        int k0 = kt * 32;
        uint32_t ws = sbase + (uint32_t)s*GSTAGEh*2;
        uint32_t xs = ws + WSTh*2;
        #pragma unroll
        for (int i = 0; i < 2; i++) {                  // W: 256 x 32, 1024 cp / 512 thr
            int idx = tid + i*512;
            int m = idx >> 2, ch = idx & 3;
            cpasync16(ws + (m*WSPh + ch*8)*2, &Wh[(size_t)m*Cq + k0 + ch*8]);
        }
        {                                              // X: 32 x 128, 512 cp / 512 thr
            int k = tid >> 4, ch = tid & 15;
            cpasync16(xs + (k*XSPh + ch*8)*2, &Xb[(size_t)(k0 + k)*TVq + n0 + ch*8]);
        }
        CP_COMMIT();
    };

    load_stage(0, 0);
    load_stage(1, 1);
    load_stage(2, 2);

    #pragma unroll
    for (int kt = 0; kt < 8; kt++) {
        // exact drain: group kt must be complete before reading its stage.
        if (kt == 7)      { CP_WAIT(0); }
        else if (kt == 6) { CP_WAIT(1); }
        else              { CP_WAIT(2); }
        __syncthreads();
        if (kt + 3 < 8) load_stage(kt + 3, (kt + 3) % NSTAGE);

        uint32_t ws = sbase + (uint32_t)(kt % NSTAGE)*GSTAGEh*2;
        uint32_t xs = ws + WSTh*2;

        #pragma unroll
        for (int ks = 0; ks < 2; ks++) {
            uint32_t Af[4][4];
            #pragma unroll
            for (int mi = 0; mi < 4; mi++)
                ldsm_x4(Af[mi][0], Af[mi][1], Af[mi][2], Af[mi][3],
                        ws + ((wm*64 + mi*16 + l16)*WSPh + ks*16 + 8*lh)*2);
            uint32_t Bf[2][4];
            #pragma unroll
            for (int p = 0; p < 2; p++)
                ldsm_x4_t(Bf[p][0], Bf[p][1], Bf[p][2], Bf[p][3],
                          xs + ((ks*16 + l16)*XSPh + wn*32 + p*16 + 8*lh)*2);
            #pragma unroll
            for (int mi = 0; mi < 4; mi++)
                #pragma unroll
                for (int p = 0; p < 2; p++) {
                    mma_f16(acc[mi][2*p],   Af[mi][0], Af[mi][1], Af[mi][2], Af[mi][3],
                            Bf[p][0], Bf[p][1]);
                    mma_f16(acc[mi][2*p+1], Af[mi][0], Af[mi][1], Af[mi][2], Af[mi][3],
                            Bf[p][2], Bf[p][3]);
                }
        }
        __syncthreads();
    }

    // epilogue: fp16 store + deterministic BN partials
    __half* Yb = g_bufAh + (size_t)b*Oq*TVq;
    #pragma unroll
    for (int mi = 0; mi < 4; mi++) {
        #pragma unroll
        for (int h = 0; h < 2; h++) {
            int row = wm*64 + mi*16 + h*8 + r;
            float s = 0.f, q = 0.f;
            #pragma unroll
            for (int ni = 0; ni < 4; ni++) {
                float v0 = acc[mi][ni][2*h], v1 = acc[mi][ni][2*h + 1];
                s += v0 + v1;
                q  = fmaf(v0, v0, fmaf(v1, v1, q));
                int col = n0 + wn*32 + ni*8 + 2*c;
                *(__half2*)&Yb[(size_t)row*TVq + col] = __floats2half2_rn(v0, v1);
            }
            s += __shfl_xor_sync(0xffffffffu, s, 1);
            s += __shfl_xor_sync(0xffffffffu, s, 2);
            q += __shfl_xor_sync(0xffffffffu, q, 1);
            q += __shfl_xor_sync(0xffffffffu, q, 2);
            if (c == 0) {
                sred[0][row][wn] = s;
                sred[1][row][wn] = q;
            }
        }
    }
    __syncthreads();
    if (tid < 256) {
        int blk = blockIdx.z*64 + blockIdx.x;          // 0..1023
        g_psum[part][blk][tid] = (sred[0][tid][0] + sred[0][tid][1])
                               + (sred[0][tid][2] + sred[0][tid][3]);
        g_psq [part][blk][tid] = (sred[1][tid][0] + sred[1][tid][1])
                               + (sred[1][tid][2] + sred[1][tid][3]);
    }
}

// deterministic reduction of BN partials -> g_stats
__global__ void k_redstats(int part) {
    int o = blockIdx.x, tid = threadIdx.x;
    float s = 0.f, q = 0.f;
    #pragma unroll
    for (int i = 0; i < 4; i++) {
        s += g_psum[part][tid + i*256][o];
        q += g_psq [part][tid + i*256][o];
    }
    __shared__ float ss[256], qq[256];
    ss[tid] = s; qq[tid] = q;
    __syncthreads();
    for (int st = 128; st > 0; st >>= 1) {
        if (tid < st) { ss[tid] += ss[tid + st]; qq[tid] += qq[tid + st]; }
        __syncthreads();
    }
    if (tid == 0) {
        g_stats[part*2*Oq + o]      = ss[0];
        g_stats[part*2*Oq + Oq + o] = qq[0];
    }
}

// ---------------- stage5 ----------------
#define HSPh 72
#define ASPh 72
#define S5H (128*HSPh + 64*ASPh)

__global__ void __launch_bounds__(256) k_stage5(const float* __restrict__ alpha_p,
                                                const float* __restrict__ gamma,
                                                const float* __restrict__ beta) {
    extern __shared__ __align__(16) char smraw[];
    __half* hs = (__half*)smraw;
    __half* As = hs + 128*HSPh;

    int bx = blockIdx.x;
    int b = bx >> 8, o = bx & 255, k = o >> 5;
    int tid  = threadIdx.x;
    int warp = tid >> 5, lane = tid & 31;
    int wm = warp >> 1, wn = warp & 1;
    int r  = lane >> 2, c = lane & 3;
    int l16 = lane & 15, lh = lane >> 4;

    float mean  = g_stats[o]      * (1.f/CNT);
    float var   = g_stats[Oq + o] * (1.f/CNT) - mean*mean;
    float scale = gamma[o] * rsqrtf(var + 1e-5f);
    float shift = beta[o] - mean*scale;

    const __half* src = g_bufAh + (size_t)bx*TVq;
    for (int i = tid; i < TVq/8; i += 256) {
        int t = (i*8) >> 6, v = (i*8) & 63;
        const __half2* s2 = (const __half2*)(src + i*8);
        __half2 out[4];
        #pragma unroll
        for (int j = 0; j < 4; j++) {
            float2 f = __half22float2(s2[j]);
            out[j] = __floats2half2_rn(fmaxf(fmaf(f.x, scale, shift), 0.f),
                                       fmaxf(fmaf(f.y, scale, shift), 0.f));
        }
        *(uint2*)&hs[t*HSPh + v]     = *(uint2*)&out[0];
        *(uint2*)&hs[t*HSPh + v + 4] = *(uint2*)&out[2];
    }

    float alpha = alpha_p[0];
    const float* x1r = g_x1 + bx*Vq;
    const float* x2r = g_x2 + bx*Vq;
    const float* Mp  = g_M + (size_t)(b*Kq + k)*Vq*Vq;
    for (int i = tid; i < Vq*Vq; i += 256) {
        int v = i >> 6, w = i & 63;
        As[v*ASPh + w] = __float2half(Mp[i] + alpha * tanhf(x1r[v] - x2r[w]));
    }
    __syncthreads();

    uint32_t hsb = (uint32_t)__cvta_generic_to_shared(hs);
    uint32_t asb = (uint32_t)__cvta_generic_to_shared(As);

    float acc[2][4][4];
    #pragma unroll
    for (int i = 0; i < 2; i++)
        #pragma unroll
        for (int j = 0; j < 4; j++)
            #pragma unroll
            for (int q = 0; q < 4; q++) acc[i][j][q] = 0.f;

    #pragma unroll
    for (int ks = 0; ks < 4; ks++) {
        uint32_t Af[2][4];
        #pragma unroll
        for (int mi = 0; mi < 2; mi++)
            ldsm_x4(Af[mi][0], Af[mi][1], Af[mi][2], Af[mi][3],
                    hsb + ((wm*32 + mi*16 + l16)*HSPh + ks*16 + 8*lh)*2);
        uint32_t Bf[2][4];
        #pragma unroll
        for (int p = 0; p < 2; p++)
            ldsm_x4_t(Bf[p][0], Bf[p][1], Bf[p][2], Bf[p][3],
                      asb + ((ks*16 + l16)*ASPh + wn*32 + p*16 + 8*lh)*2);
        #pragma unroll
        for (int mi = 0; mi < 2; mi++)
            #pragma unroll
            for (int p = 0; p < 2; p++) {
                mma_f16(acc[mi][2*p],   Af[mi][0], Af[mi][1], Af[mi][2], Af[mi][3],
                        Bf[p][0], Bf[p][1]);
                mma_f16(acc[mi][2*p+1], Af[mi][0], Af[mi][1], Af[mi][2], Af[mi][3],
                        Bf[p][2], Bf[p][3]);
            }
    }

    __half* dst = g_bufBh + (size_t)bx*TVq;
    #pragma unroll
    for (int mi = 0; mi < 2; mi++) {
        int row = wm*32 + mi*16 + r;
        #pragma unroll
        for (int ni = 0; ni < 4; ni++) {
            int col = wn*32 + ni*8 + 2*c;
            *(__half2*)&dst[row*Vq + col]       = __floats2half2_rn(acc[mi][ni][0], acc[mi][ni][1]);
            *(__half2*)&dst[(row + 8)*Vq + col] = __floats2half2_rn(acc[mi][ni][2], acc[mi][ni][3]);
        }
    }
}

// out = relu(BN(z) + x)
__global__ void k_out(const float* __restrict__ gamma, const float* __restrict__ beta,
                      float* __restrict__ out) {
    size_t base = (size_t)blockIdx.x * 1024 + threadIdx.x;
    const __half2* zph = (const __half2*)(g_bufAh);
    const __half2* xph = (const __half2*)(g_xh);

    __half2 z[4][2], xv[4][2];
    #pragma unroll
    for (int j = 0; j < 4; j++) {
        size_t i4 = base + j*256;
        z[j][0]  = zph[i4*2];     z[j][1]  = zph[i4*2 + 1];
        xv[j][0] = xph[i4*2];     xv[j][1] = xph[i4*2 + 1];
    }
    #pragma unroll
    for (int j = 0; j < 4; j++) {
        size_t i4 = base + j*256;
        int o = (int)((i4 >> 11) & 255);
        float mean  = g_stats[2*Oq + o] * (1.f/CNT);
        float var   = g_stats[3*Oq + o] * (1.f/CNT) - mean*mean;
        float scale = gamma[o] * rsqrtf(var + 1e-5f);
        float shift = beta[o] - mean*scale;
        float2 z0 = __half22float2(z[j][0]);
        float2 z1 = __half22float2(z[j][1]);
        float2 x0 = __half22float2(xv[j][0]);
        float2 x1 = __half22float2(xv[j][1]);
        float4 rr;
        rr.x = fmaxf(fmaf(z0.x, scale, shift) + x0.x, 0.f);
        rr.y = fmaxf(fmaf(z0.y, scale, shift) + x0.y, 0.f);
        rr.z = fmaxf(fmaf(z1.x, scale, shift) + x1.x, 0.f);
        rr.w = fmaxf(fmaf(z1.y, scale, shift) + x1.y, 0.f);
        ((float4*)out)[i4] = rr;
    }
}

// ---------------- launch ----------------
extern "C" void kernel_launch(void* const* d_in, const int* in_sizes, int n_in,
                              void* d_out, int out_size) {
    const float* x       = (const float*)d_in[0];
    const float* A_param = (const float*)d_in[1];
    const float* alpha   = (const float*)d_in[2];
    const float* beta    = (const float*)d_in[3];
    const float* w1      = (const float*)d_in[4];
    const float* b1      = (const float*)d_in[5];
    const float* w2      = (const float*)d_in[6];
    const float* b2      = (const float*)d_in[7];
    const float* stem_w  = (const float*)d_in[8];
    const float* stem_g  = (const float*)d_in[10];
    const float* stem_be = (const float*)d_in[11];
    const float* head_w  = (const float*)d_in[12];
    const float* head_g  = (const float*)d_in[14];
    const float* head_be = (const float*)d_in[15];
    float* out = (float*)d_out;

    int gemm_smem   = NSTAGE * GSTAGEh * 2;   // 116736 B
    int stage5_smem = S5H * 2;                // 27648 B
    cudaFuncSetAttribute(k_gemm,   cudaFuncAttributeMaxDynamicSharedMemorySize, gemm_smem);
    cudaFuncSetAttribute(k_stage5, cudaFuncAttributeMaxDynamicSharedMemorySize, stage5_smem);

    __half* whp = nullptr;  cudaGetSymbolAddress((void**)&whp, g_wh);
    __half* xhp = nullptr;  cudaGetSymbolAddress((void**)&xhp, g_xh);
    __half* bBp = nullptr;  cudaGetSymbolAddress((void**)&bBp, g_bufBh);

    k_meanT<<<Bq*Cq + 256, 256>>>(x, stem_w, head_w);
    k_x1x2<<<dim3(Oq/16, Bq), 256>>>(w1, b1, w2, b2);
    k_adj<<<Bq*Kq, 256>>>(A_param, beta);

    // stem conv + deterministic BN partials (bias cancels in BN)
    k_gemm<<<dim3(TVq/128, 1, Bq), 512, gemm_smem>>>(whp, xhp, 0);
    k_redstats<<<Oq, 256>>>(0);

    // BN+relu + graph matmul
    k_stage5<<<Bq*Oq, 256, stage5_smem>>>(alpha, stem_g, stem_be);

    // head conv + deterministic BN partials
    k_gemm<<<dim3(TVq/128, 1, Bq), 512, gemm_smem>>>(whp + Oq*Cq, bBp, 1);
    k_redstats<<<Oq, 256>>>(1);

    k_out<<<(int)(((size_t)Bq*Oq*TVq/4)/1024), 256>>>(head_g, head_be, out);
}

// round 12
// speedup vs baseline: 1.0721x; 1.0721x over previous
#include <cuda_runtime.h>
#include <cuda_fp16.h>
#include <cmath>
#include <cstdint>

#define Bq 16
#define Cq 256
#define Tq 128
#define Vq 64
#define Kq 8
#define Oq 256
#define TVq 8192
#define CNT 131072
#define NBLK 1024            // GEMM blocks per launch = 64 * 16

// ---------------- scratch ----------------
// g_xh / g_bufBh / g_wh are stored TILE-PACKED + PRE-SWIZZLED for TMA bulk loads:
//   X (per b): [stage s=c>>6][nb=tv>>7][kr=c&63][nc^((kr&7)<<3)]  (tile = 16KB)
//   W:         [stage s=k>>6][m][ (k&63) ^ ((m&7)<<3) ]           (stage = 32KB)
__device__ float  g_tp[Bq*Cq*Vq];
__device__ float  g_x1[Bq*Oq*Vq];
__device__ float  g_x2[Bq*Oq*Vq];
__device__ float  g_M [Bq*Kq*Vq*Vq];
__device__ float  g_stats[4*Oq];
__device__ float  g_psum[2][NBLK][Oq];
__device__ float  g_psq [2][NBLK][Oq];
__device__ __align__(128) __half g_xh  [(size_t)Bq*Cq*TVq];
__device__ __align__(128) __half g_bufAh[(size_t)Bq*Oq*TVq];  // linear [b][o][tv]
__device__ __align__(128) __half g_bufBh[(size_t)Bq*Oq*TVq];  // packed (see above)
__device__ __align__(128) __half g_wh[2*Oq*Cq];               // packed per weight

// ---------------- helpers ----------------
__device__ __forceinline__ void mma_f16(float c[4],
                                        uint32_t a0, uint32_t a1, uint32_t a2, uint32_t a3,
                                        uint32_t b0, uint32_t b1) {
    asm volatile(
        "mma.sync.aligned.m16n8k16.row.col.f32.f16.f16.f32 "
        "{%0,%1,%2,%3},{%4,%5,%6,%7},{%8,%9},{%0,%1,%2,%3};\n"
        : "+f"(c[0]), "+f"(c[1]), "+f"(c[2]), "+f"(c[3])
        : "r"(a0), "r"(a1), "r"(a2), "r"(a3), "r"(b0), "r"(b1));
}
__device__ __forceinline__ void ldsm_x4(uint32_t& r0, uint32_t& r1, uint32_t& r2, uint32_t& r3,
                                        uint32_t addr) {
    asm volatile("ldmatrix.sync.aligned.m8n8.x4.shared.b16 {%0,%1,%2,%3}, [%4];\n"
                 : "=r"(r0), "=r"(r1), "=r"(r2), "=r"(r3) : "r"(addr));
}
__device__ __forceinline__ void ldsm_x4_t(uint32_t& r0, uint32_t& r1, uint32_t& r2, uint32_t& r3,
                                          uint32_t addr) {
    asm volatile("ldmatrix.sync.aligned.m8n8.x4.trans.shared.b16 {%0,%1,%2,%3}, [%4];\n"
                 : "=r"(r0), "=r"(r1), "=r"(r2), "=r"(r3) : "r"(addr));
}
__device__ __forceinline__ void cpbulk(uint32_t dst, const void* src, uint32_t bytes, uint32_t mbar) {
    asm volatile("cp.async.bulk.shared::cta.global.mbarrier::complete_tx::bytes [%0], [%1], %2, [%3];\n"
                 :: "r"(dst), "l"(src), "r"(bytes), "r"(mbar) : "memory");
}
#define MBAR_INIT(addr, cnt) \
    asm volatile("mbarrier.init.shared.b64 [%0], %1;" :: "r"(addr), "r"(cnt) : "memory")
#define MBAR_EXPECT_TX(addr, bytes) \
    asm volatile("mbarrier.arrive.expect_tx.shared.b64 _, [%0], %1;" :: "r"(addr), "r"(bytes) : "memory")
#define MBAR_WAIT(addr, parity) do {                                                   \
    uint32_t _m = (addr), _p = (parity), _d;                                           \
    asm volatile("{\n\t.reg .pred p;\n\t"                                              \
        "mbarrier.try_wait.parity.acquire.cta.shared::cta.b64 p, [%1], %2;\n\t"        \
        "selp.b32 %0, 1, 0, p;\n\t}" : "=r"(_d) : "r"(_m), "r"(_p) : "memory");        \
    if (!_d) {                                                                         \
        asm volatile("{\n\t.reg .pred P1;\n\t"                                         \
            "WL_%=:\n\t"                                                               \
            "mbarrier.try_wait.parity.acquire.cta.shared::cta.b64 P1, [%0], %1, 0x989680;\n\t" \
            "@P1 bra.uni WD_%=;\n\t"                                                   \
            "bra.uni WL_%=;\n\t"                                                       \
            "WD_%=:\n\t}" :: "r"(_m), "r"(_p) : "memory");                             \
    }                                                                                  \
} while (0)

// x -> packed/swizzled fp16 copy + per-(b,c) mean over T; extra blocks pack weights
__global__ void k_meanT(const float* __restrict__ x,
                        const float* __restrict__ sw, const float* __restrict__ hw) {
    int bc = blockIdx.x;
    int tid = threadIdx.x;
    if (bc >= Bq*Cq) {                    // weight-packing blocks
        int i = (bc - Bq*Cq)*256 + tid;   // i = m*256 + k  over 65536
        int m = i >> 8, k = i & 255;
        int hoff = (k >> 6)*16384 + m*64 + ((k & 63) ^ ((m & 7) << 3));
        g_wh[hoff]              = __float2half(sw[i]);
        g_wh[Oq*Cq + hoff]      = __float2half(hw[i]);
        return;
    }
    int lane = tid & 31, warp = tid >> 5;
    int b = bc >> 8, c = bc & 255;
    int s = c >> 6, kr = c & 63;
    __shared__ float red[8][64];
    const float4* p = (const float4*)(x + (size_t)bc*TVq);
    // packed tile base for (b, s, kr): halfs
    size_t xbase = ((size_t)(b*4 + s)*64) * 8192 + (size_t)kr*128;
    int swz = (kr & 7) << 3;
    float s0=0.f, s1=0.f, s2=0.f, s3=0.f;
    int v0 = (tid*4) & 63;
    #pragma unroll
    for (int i = 0; i < 8; i++) {
        int e = tid + i*256;              // float4 index; tv0 = e*4
        float4 f = p[e];
        s0 += f.x; s1 += f.y; s2 += f.z; s3 += f.w;
        int tv0 = e*4;
        int nb = tv0 >> 7, nc = tv0 & 127;
        size_t hoff = xbase + (size_t)nb*8192 + (nc ^ swz);
        __half2 h0 = __floats2half2_rn(f.x, f.y);
        __half2 h1 = __floats2half2_rn(f.z, f.w);
        uint2 u; u.x = *(uint32_t*)&h0; u.y = *(uint32_t*)&h1;
        *(uint2*)&g_xh[hoff] = u;
    }
    s0 += __shfl_xor_sync(0xffffffffu, s0, 16);
    s1 += __shfl_xor_sync(0xffffffffu, s1, 16);
    s2 += __shfl_xor_sync(0xffffffffu, s2, 16);
    s3 += __shfl_xor_sync(0xffffffffu, s3, 16);
    if (lane < 16) {
        red[warp][v0]   = s0;
        red[warp][v0+1] = s1;
        red[warp][v0+2] = s2;
        red[warp][v0+3] = s3;
    }
    __syncthreads();
    if (tid < 64) {
        float ss = 0.f;
        #pragma unroll
        for (int w = 0; w < 8; w++) ss += red[w][tid];
        g_tp[bc*Vq + tid] = ss * (1.f/Tq);
    }
}

// x1/x2 = conv1x1(tp) — tiled
__global__ void __launch_bounds__(256) k_x1x2(const float* __restrict__ w1, const float* __restrict__ b1,
                                              const float* __restrict__ w2, const float* __restrict__ b2) {
    __shared__ float tps[64][64];
    __shared__ float w1s[16][64];
    __shared__ float w2s[16][64];
    int b = blockIdx.y, ot = blockIdx.x * 16;
    int tid = threadIdx.x;
    int v = tid & 63, og = tid >> 6;
    float a1[4] = {0.f,0.f,0.f,0.f}, a2[4] = {0.f,0.f,0.f,0.f};

    for (int c0 = 0; c0 < Cq; c0 += 64) {
        __syncthreads();
        #pragma unroll
        for (int i = 0; i < 16; i++) {
            int idx = tid + i*256;
            tps[idx >> 6][idx & 63] = g_tp[(b*Cq + c0 + (idx >> 6))*Vq + (idx & 63)];
        }
        #pragma unroll
        for (int i = 0; i < 4; i++) {
            int idx = tid + i*256;
            int o = idx >> 6, cc = idx & 63;
            w1s[o][cc] = w1[(ot + o)*Cq + c0 + cc];
            w2s[o][cc] = w2[(ot + o)*Cq + c0 + cc];
        }
        __syncthreads();
        #pragma unroll 8
        for (int cc = 0; cc < 64; cc++) {
            float t = tps[cc][v];
            #pragma unroll
            for (int j = 0; j < 4; j++) {
                a1[j] = fmaf(t, w1s[og*4 + j][cc], a1[j]);
                a2[j] = fmaf(t, w2s[og*4 + j][cc], a2[j]);
            }
        }
    }
    #pragma unroll
    for (int j = 0; j < 4; j++) {
        int o = ot + og*4 + j;
        g_x1[(b*Oq + o)*Vq + v] = a1[j] + b1[o];
        g_x2[(b*Oq + o)*Vq + v] = a2[j] + b2[o];
    }
}

// M = A_param + beta * softmax
__global__ void k_adj(const float* __restrict__ Ap, const float* __restrict__ beta_p) {
    __shared__ float x1s[32][Vq];
    __shared__ float x2s[32][Vq];
    __shared__ float S[Vq][Vq];
    __shared__ float mred[4][64];
    __shared__ float sred2[4][64];
    int bk = blockIdx.x;
    int b = bk >> 3, k = bk & 7;
    int tid = threadIdx.x;

    for (int i = tid; i < 32*Vq; i += 256) {
        int c = i >> 6, v = i & 63;
        int row = (b*Oq + k*32 + c)*Vq + v;
        x1s[c][v] = g_x1[row];
        x2s[c][v] = g_x2[row];
    }
    __syncthreads();
    for (int i = tid; i < Vq*Vq; i += 256) {
        int v = i >> 6, w = i & 63;
        float s = 0.f;
        #pragma unroll
        for (int c = 0; c < 32; c++) s = fmaf(x1s[c][v], x2s[c][w], s);
        S[v][w] = s;
    }
    __syncthreads();

    int w = tid & 63, part = tid >> 6;
    int vlo = part*16;
    float m = -1e30f;
    #pragma unroll
    for (int v = 0; v < 16; v++) m = fmaxf(m, S[vlo + v][w]);
    mred[part][w] = m;
    __syncthreads();
    m = fmaxf(fmaxf(mred[0][w], mred[1][w]), fmaxf(mred[2][w], mred[3][w]));
    float sum = 0.f;
    #pragma unroll
    for (int v = 0; v < 16; v++) {
        float e = __expf(S[vlo + v][w] - m);
        S[vlo + v][w] = e;
        sum += e;
    }
    sred2[part][w] = sum;
    __syncthreads();
    float tot = sred2[0][w] + sred2[1][w] + sred2[2][w] + sred2[3][w];
    float scl = beta_p[0] / tot;
    #pragma unroll
    for (int v = 0; v < 16; v++) {
        int vv = vlo + v;
        g_M[((bk*Vq + vv) << 6) + w] = Ap[((k*Vq + vv) << 6) + w] + S[vv][w]*scl;
    }
}

// ---------------- fp16 GEMM via TMA bulk loads of packed tiles ----------------
// smem: W stages 0..3 at s*32768 (32KB each), X stages at 131072 + s*16384 (16KB),
// mbarriers at 196608. All 4 stages loaded upfront; no ring/reuse.
#define GEMM_SMEM (196608 + 64)

__global__ void __launch_bounds__(512, 1) k_gemm(const __half* __restrict__ Wh,
                                                 const __half* __restrict__ Xg,
                                                 int part) {
    extern __shared__ __align__(128) char smraw[];
    __shared__ float sred[2][256][4];
    int b  = blockIdx.z;
    int nb = blockIdx.x;
    int n0 = nb * 128;
    int tid  = threadIdx.x;
    int warp = tid >> 5, lane = tid & 31;
    int wm = warp >> 2, wn = warp & 3;           // 4 x 4 warps, warp tile 64m x 32n
    int r  = lane >> 2, c = lane & 3;
    int l16 = lane & 15, lh = lane >> 4;

    uint32_t sbase = (uint32_t)__cvta_generic_to_shared(smraw);
    uint32_t mbar  = sbase + 196608;

    if (tid == 0) {
        #pragma unroll
        for (int s = 0; s < 4; s++) MBAR_INIT(mbar + s*8, 1);
    }
    __syncthreads();
    if (tid == 0) {
        const char* wsrc = (const char*)Wh;
        const char* xsrc = (const char*)Xg + ((size_t)(b*4)*64 + nb) * 16384;
        #pragma unroll
        for (int s = 0; s < 4; s++) {
            MBAR_EXPECT_TX(mbar + s*8, 49152);
            cpbulk(sbase + s*32768,            wsrc + (size_t)s*32768,        32768, mbar + s*8);
            cpbulk(sbase + 131072 + s*16384,   xsrc + (size_t)s*64*16384,     16384, mbar + s*8);
        }
    }

    float acc[4][4][4];
    #pragma unroll
    for (int i = 0; i < 4; i++)
        #pragma unroll
        for (int j = 0; j < 4; j++)
            #pragma unroll
            for (int q = 0; q < 4; q++) acc[i][j][q] = 0.f;

    #pragma unroll
    for (int kt = 0; kt < 4; kt++) {
        MBAR_WAIT(mbar + kt*8, 0);
        uint32_t wsb = sbase + kt*32768;
        uint32_t xsb = sbase + 131072 + kt*16384;

        #pragma unroll
        for (int ks = 0; ks < 4; ks++) {
            uint32_t Af[4][4];
            #pragma unroll
            for (int mi = 0; mi < 4; mi++) {
                int m = wm*64 + mi*16 + l16;
                uint32_t a = wsb + m*128 + (((uint32_t)(ks*32 + lh*16)) ^ (((uint32_t)(m & 7)) << 4));
                ldsm_x4(Af[mi][0], Af[mi][1], Af[mi][2], Af[mi][3], a);
            }
            uint32_t Bf[2][4];
            #pragma unroll
            for (int p = 0; p < 2; p++) {
                int k = ks*16 + l16;
                int np = wn*32 + p*16 + lh*8;
                uint32_t a = xsb + k*256 + (((uint32_t)(np*2)) ^ (((uint32_t)(k & 7)) << 4));
                ldsm_x4_t(Bf[p][0], Bf[p][1], Bf[p][2], Bf[p][3], a);
            }
            #pragma unroll
            for (int mi = 0; mi < 4; mi++)
                #pragma unroll
                for (int p = 0; p < 2; p++) {
                    mma_f16(acc[mi][2*p],   Af[mi][0], Af[mi][1], Af[mi][2], Af[mi][3],
                            Bf[p][0], Bf[p][1]);
                    mma_f16(acc[mi][2*p+1], Af[mi][0], Af[mi][1], Af[mi][2], Af[mi][3],
                            Bf[p][2], Bf[p][3]);
                }
        }
    }

    // epilogue: fp16 linear store + deterministic BN partials
    __half* Yb = g_bufAh + (size_t)b*Oq*TVq;
    #pragma unroll
    for (int mi = 0; mi < 4; mi++) {
        #pragma unroll
        for (int h = 0; h < 2; h++) {
            int row = wm*64 + mi*16 + h*8 + r;
            float s = 0.f, q = 0.f;
            #pragma unroll
            for (int ni = 0; ni < 4; ni++) {
                float v0 = acc[mi][ni][2*h], v1 = acc[mi][ni][2*h + 1];
                s += v0 + v1;
                q  = fmaf(v0, v0, fmaf(v1, v1, q));
                int col = n0 + wn*32 + ni*8 + 2*c;
                *(__half2*)&Yb[(size_t)row*TVq + col] = __floats2half2_rn(v0, v1);
            }
            s += __shfl_xor_sync(0xffffffffu, s, 1);
            s += __shfl_xor_sync(0xffffffffu, s, 2);
            q += __shfl_xor_sync(0xffffffffu, q, 1);
            q += __shfl_xor_sync(0xffffffffu, q, 2);
            if (c == 0) {
                sred[0][row][wn] = s;
                sred[1][row][wn] = q;
            }
        }
    }
    __syncthreads();
    if (tid < 256) {
        int blk = blockIdx.z*64 + blockIdx.x;
        g_psum[part][blk][tid] = (sred[0][tid][0] + sred[0][tid][1])
                               + (sred[0][tid][2] + sred[0][tid][3]);
        g_psq [part][blk][tid] = (sred[1][tid][0] + sred[1][tid][1])
                               + (sred[1][tid][2] + sred[1][tid][3]);
    }
}

// deterministic reduction of BN partials -> g_stats
__global__ void k_redstats(int part) {
    int o = blockIdx.x, tid = threadIdx.x;
    float s = 0.f, q = 0.f;
    #pragma unroll
    for (int i = 0; i < 4; i++) {
        s += g_psum[part][tid + i*256][o];
        q += g_psq [part][tid + i*256][o];
    }
    __shared__ float ss[256], qq[256];
    ss[tid] = s; qq[tid] = q;
    __syncthreads();
    for (int st = 128; st > 0; st >>= 1) {
        if (tid < st) { ss[tid] += ss[tid + st]; qq[tid] += qq[tid + st]; }
        __syncthreads();
    }
    if (tid == 0) {
        g_stats[part*2*Oq + o]      = ss[0];
        g_stats[part*2*Oq + Oq + o] = qq[0];
    }
}

// ---------------- stage5 ----------------
#define HSPh 72
#define ASPh 72
#define S5H (128*HSPh + 64*ASPh)

__global__ void __launch_bounds__(256) k_stage5(const float* __restrict__ alpha_p,
                                                const float* __restrict__ gamma,
                                                const float* __restrict__ beta) {
    extern __shared__ char smraw[];
    __half* hs = (__half*)smraw;
    __half* As = hs + 128*HSPh;

    int bx = blockIdx.x;
    int b = bx >> 8, o = bx & 255, kk = o >> 5;
    int tid  = threadIdx.x;
    int warp = tid >> 5, lane = tid & 31;
    int wm = warp >> 1, wn = warp & 1;
    int r  = lane >> 2, c = lane & 3;
    int l16 = lane & 15, lh = lane >> 4;

    float mean  = g_stats[o]      * (1.f/CNT);
    float var   = g_stats[Oq + o] * (1.f/CNT) - mean*mean;
    float scale = gamma[o] * rsqrtf(var + 1e-5f);
    float shift = beta[o] - mean*scale;

    const __half* src = g_bufAh + (size_t)bx*TVq;
    for (int i = tid; i < TVq/8; i += 256) {
        int t = (i*8) >> 6, v = (i*8) & 63;
        const __half2* s2 = (const __half2*)(src + i*8);
        __half2 out[4];
        #pragma unroll
        for (int j = 0; j < 4; j++) {
            float2 f = __half22float2(s2[j]);
            out[j] = __floats2half2_rn(fmaxf(fmaf(f.x, scale, shift), 0.f),
                                       fmaxf(fmaf(f.y, scale, shift), 0.f));
        }
        *(uint2*)&hs[t*HSPh + v]     = *(uint2*)&out[0];
        *(uint2*)&hs[t*HSPh + v + 4] = *(uint2*)&out[2];
    }

    float alpha = alpha_p[0];
    const float* x1r = g_x1 + bx*Vq;
    const float* x2r = g_x2 + bx*Vq;
    const float* Mp  = g_M + (size_t)(b*Kq + kk)*Vq*Vq;
    for (int i = tid; i < Vq*Vq; i += 256) {
        int v = i >> 6, w = i & 63;
        As[v*ASPh + w] = __float2half(Mp[i] + alpha * tanhf(x1r[v] - x2r[w]));
    }
    __syncthreads();

    uint32_t hsb = (uint32_t)__cvta_generic_to_shared(hs);
    uint32_t asb = (uint32_t)__cvta_generic_to_shared(As);

    float acc[2][4][4];
    #pragma unroll
    for (int i = 0; i < 2; i++)
        #pragma unroll
        for (int j = 0; j < 4; j++)
            #pragma unroll
            for (int q = 0; q < 4; q++) acc[i][j][q] = 0.f;

    #pragma unroll
    for (int ks = 0; ks < 4; ks++) {
        uint32_t Af[2][4];
        #pragma unroll
        for (int mi = 0; mi < 2; mi++)
            ldsm_x4(Af[mi][0], Af[mi][1], Af[mi][2], Af[mi][3],
                    hsb + ((wm*32 + mi*16 + l16)*HSPh + ks*16 + 8*lh)*2);
        uint32_t Bf[2][4];
        #pragma unroll
        for (int p = 0; p < 2; p++)
            ldsm_x4_t(Bf[p][0], Bf[p][1], Bf[p][2], Bf[p][3],
                      asb + ((ks*16 + l16)*ASPh + wn*32 + p*16 + 8*lh)*2);
        #pragma unroll
        for (int mi = 0; mi < 2; mi++)
            #pragma unroll
            for (int p = 0; p < 2; p++) {
                mma_f16(acc[mi][2*p],   Af[mi][0], Af[mi][1], Af[mi][2], Af[mi][3],
                        Bf[p][0], Bf[p][1]);
                mma_f16(acc[mi][2*p+1], Af[mi][0], Af[mi][1], Af[mi][2], Af[mi][3],
                        Bf[p][2], Bf[p][3]);
            }
    }

    // write packed+swizzled for head-GEMM TMA: s = o>>6, kr = o&63
    {
        int s = o >> 6, kr = o & 63;
        int swz = (kr & 7) << 3;
        __half* dstb = g_bufBh + ((size_t)(b*4 + s)*64) * 8192 + (size_t)kr*128;
        #pragma unroll
        for (int mi = 0; mi < 2; mi++) {
            #pragma unroll
            for (int h = 0; h < 2; h++) {
                int t = wm*32 + mi*16 + h*8 + r;
                int nb = t >> 1;
                #pragma unroll
                for (int ni = 0; ni < 4; ni++) {
                    int w = wn*32 + ni*8 + 2*c;
                    int nc = (t & 1)*64 + w;
                    size_t hoff = (size_t)nb*8192 + (nc ^ swz);
                    *(__half2*)&dstb[hoff] = __floats2half2_rn(acc[mi][ni][2*h], acc[mi][ni][2*h+1]);
                }
            }
        }
    }
}

// out = relu(BN(z) + x); z linear fp16, residual x from PACKED g_xh
__global__ void k_out(const float* __restrict__ gamma, const float* __restrict__ beta,
                      float* __restrict__ out) {
    size_t base = (size_t)blockIdx.x * 1024 + threadIdx.x;
    const __half2* zph = (const __half2*)(g_bufAh);

    __half2 z[4][2], xv[4][2];
    #pragma unroll
    for (int j = 0; j < 4; j++) {
        size_t i4 = base + j*256;
        z[j][0] = zph[i4*2];  z[j][1] = zph[i4*2 + 1];
        size_t e = i4*4;
        int bb = (int)(e >> 21);
        int cc = (int)((e >> 13) & 255);
        int tv = (int)(e & 8191);
        int s = cc >> 6, kr = cc & 63;
        int nb = tv >> 7, nc = tv & 127;
        size_t hoff = ((size_t)(bb*4 + s)*64 + nb)*8192 + kr*128 + (nc ^ ((kr & 7) << 3));
        uint2 u = *(const uint2*)&g_xh[hoff];
        xv[j][0] = *(__half2*)&u.x;
        xv[j][1] = *(__half2*)&u.y;
    }
    #pragma unroll
    for (int j = 0; j < 4; j++) {
        size_t i4 = base + j*256;
        int o = (int)((i4 >> 11) & 255);
        float mean  = g_stats[2*Oq + o] * (1.f/CNT);
        float var   = g_stats[3*Oq + o] * (1.f/CNT) - mean*mean;
        float scale = gamma[o] * rsqrtf(var + 1e-5f);
        float shift = beta[o] - mean*scale;
        float2 z0 = __half22float2(z[j][0]);
        float2 z1 = __half22float2(z[j][1]);
        float2 x0 = __half22float2(xv[j][0]);
        float2 x1 = __half22float2(xv[j][1]);
        float4 rr;
        rr.x = fmaxf(fmaf(z0.x, scale, shift) + x0.x, 0.f);
        rr.y = fmaxf(fmaf(z0.y, scale, shift) + x0.y, 0.f);
        rr.z = fmaxf(fmaf(z1.x, scale, shift) + x1.x, 0.f);
        rr.w = fmaxf(fmaf(z1.y, scale, shift) + x1.y, 0.f);
        ((float4*)out)[i4] = rr;
    }
}

// ---------------- launch ----------------
extern "C" void kernel_launch(void* const* d_in, const int* in_sizes, int n_in,
                              void* d_out, int out_size) {
    const float* x       = (const float*)d_in[0];
    const float* A_param = (const float*)d_in[1];
    const float* alpha   = (const float*)d_in[2];
    const float* beta    = (const float*)d_in[3];
    const float* w1      = (const float*)d_in[4];
    const float* b1      = (const float*)d_in[5];
    const float* w2      = (const float*)d_in[6];
    const float* b2      = (const float*)d_in[7];
    const float* stem_w  = (const float*)d_in[8];
    const float* stem_g  = (const float*)d_in[10];
    const float* stem_be = (const float*)d_in[11];
    const float* head_w  = (const float*)d_in[12];
    const float* head_g  = (const float*)d_in[14];
    const float* head_be = (const float*)d_in[15];
    float* out = (float*)d_out;

    int stage5_smem = S5H * 2;
    cudaFuncSetAttribute(k_gemm,   cudaFuncAttributeMaxDynamicSharedMemorySize, GEMM_SMEM);
    cudaFuncSetAttribute(k_stage5, cudaFuncAttributeMaxDynamicSharedMemorySize, stage5_smem);

    __half* whp = nullptr;  cudaGetSymbolAddress((void**)&whp, g_wh);
    __half* xhp = nullptr;  cudaGetSymbolAddress((void**)&xhp, g_xh);
    __half* bBp = nullptr;  cudaGetSymbolAddress((void**)&bBp, g_bufBh);

    k_meanT<<<Bq*Cq + 256, 256>>>(x, stem_w, head_w);
    k_x1x2<<<dim3(Oq/16, Bq), 256>>>(w1, b1, w2, b2);
    k_adj<<<Bq*Kq, 256>>>(A_param, beta);

    // stem conv + deterministic BN partials (bias cancels in BN)
    k_gemm<<<dim3(TVq/128, 1, Bq), 512, GEMM_SMEM>>>(whp, xhp, 0);
    k_redstats<<<Oq, 256>>>(0);

    // BN+relu + graph matmul (writes packed X for head GEMM)
    k_stage5<<<Bq*Oq, 256, stage5_smem>>>(alpha, stem_g, stem_be);

    // head conv + deterministic BN partials
    k_gemm<<<dim3(TVq/128, 1, Bq), 512, GEMM_SMEM>>>(whp + Oq*Cq, bBp, 1);
    k_redstats<<<Oq, 256>>>(1);

    k_out<<<(int)(((size_t)Bq*Oq*TVq/4)/1024), 256>>>(head_g, head_be, out);
}

// round 13
// speedup vs baseline: 1.0724x; 1.0003x over previous
#include <cuda_runtime.h>
#include <cuda_fp16.h>
#include <cmath>
#include <cstdint>

#define Bq 16
#define Cq 256
#define Tq 128
#define Vq 64
#define Kq 8
#define Oq 256
#define TVq 8192
#define CNT 131072
#define NBLK 1024            // GEMM blocks per launch = 64 * 16

// ---------------- scratch ----------------
// g_xh / g_bufBh / g_wh are stored TILE-PACKED + PRE-SWIZZLED for TMA bulk loads:
//   X (per b): [stage s=c>>6][nb=tv>>7][kr=c&63][nc^((kr&7)<<3)]  (tile = 16KB)
//   W:         [stage s=k>>6][m][ (k&63) ^ ((m&7)<<3) ]           (stage = 32KB)
__device__ float  g_tp[Bq*Cq*Vq];
__device__ float  g_x1[Bq*Oq*Vq];
__device__ float  g_x2[Bq*Oq*Vq];
__device__ float  g_M [Bq*Kq*Vq*Vq];
__device__ float  g_stats[4*Oq];
__device__ float  g_psum[2][NBLK][Oq];
__device__ float  g_psq [2][NBLK][Oq];
__device__ __align__(128) __half g_xh  [(size_t)Bq*Cq*TVq];
__device__ __align__(128) __half g_bufAh[(size_t)Bq*Oq*TVq];  // linear [b][o][tv]
__device__ __align__(128) __half g_bufBh[(size_t)Bq*Oq*TVq];  // packed (see above)
__device__ __align__(128) __half g_wh[2*Oq*Cq];               // packed per weight

// ---------------- helpers ----------------
__device__ __forceinline__ void mma_f16(float c[4],
                                        uint32_t a0, uint32_t a1, uint32_t a2, uint32_t a3,
                                        uint32_t b0, uint32_t b1) {
    asm volatile(
        "mma.sync.aligned.m16n8k16.row.col.f32.f16.f16.f32 "
        "{%0,%1,%2,%3},{%4,%5,%6,%7},{%8,%9},{%0,%1,%2,%3};\n"
        : "+f"(c[0]), "+f"(c[1]), "+f"(c[2]), "+f"(c[3])
        : "r"(a0), "r"(a1), "r"(a2), "r"(a3), "r"(b0), "r"(b1));
}
__device__ __forceinline__ void ldsm_x4(uint32_t& r0, uint32_t& r1, uint32_t& r2, uint32_t& r3,
                                        uint32_t addr) {
    asm volatile("ldmatrix.sync.aligned.m8n8.x4.shared.b16 {%0,%1,%2,%3}, [%4];\n"
                 : "=r"(r0), "=r"(r1), "=r"(r2), "=r"(r3) : "r"(addr));
}
__device__ __forceinline__ void ldsm_x4_t(uint32_t& r0, uint32_t& r1, uint32_t& r2, uint32_t& r3,
                                          uint32_t addr) {
    asm volatile("ldmatrix.sync.aligned.m8n8.x4.trans.shared.b16 {%0,%1,%2,%3}, [%4];\n"
                 : "=r"(r0), "=r"(r1), "=r"(r2), "=r"(r3) : "r"(addr));
}
__device__ __forceinline__ void cpbulk(uint32_t dst, const void* src, uint32_t bytes, uint32_t mbar) {
    asm volatile("cp.async.bulk.shared::cta.global.mbarrier::complete_tx::bytes [%0], [%1], %2, [%3];\n"
                 :: "r"(dst), "l"(src), "r"(bytes), "r"(mbar) : "memory");
}
#define MBAR_INIT(addr, cnt) \
    asm volatile("mbarrier.init.shared.b64 [%0], %1;" :: "r"(addr), "r"(cnt) : "memory")
#define MBAR_EXPECT_TX(addr, bytes) \
    asm volatile("mbarrier.arrive.expect_tx.shared.b64 _, [%0], %1;" :: "r"(addr), "r"(bytes) : "memory")
#define MBAR_WAIT(addr, parity) do {                                                   \
    uint32_t _m = (addr), _p = (parity), _d;                                           \
    asm volatile("{\n\t.reg .pred p;\n\t"                                              \
        "mbarrier.try_wait.parity.acquire.cta.shared::cta.b64 p, [%1], %2;\n\t"        \
        "selp.b32 %0, 1, 0, p;\n\t}" : "=r"(_d) : "r"(_m), "r"(_p) : "memory");        \
    if (!_d) {                                                                         \
        asm volatile("{\n\t.reg .pred P1;\n\t"                                         \
            "WL_%=:\n\t"                                                               \
            "mbarrier.try_wait.parity.acquire.cta.shared::cta.b64 P1, [%0], %1, 0x989680;\n\t" \
            "@P1 bra.uni WD_%=;\n\t"                                                   \
            "bra.uni WL_%=;\n\t"                                                       \
            "WD_%=:\n\t}" :: "r"(_m), "r"(_p) : "memory");                             \
    }                                                                                  \
} while (0)

// x -> packed/swizzled fp16 copy + per-(b,c) mean over T; extra blocks pack weights
__global__ void k_meanT(const float* __restrict__ x,
                        const float* __restrict__ sw, const float* __restrict__ hw) {
    int bc = blockIdx.x;
    int tid = threadIdx.x;
    if (bc >= Bq*Cq) {                    // weight-packing blocks
        int i = (bc - Bq*Cq)*256 + tid;   // i = m*256 + k  over 65536
        int m = i >> 8, k = i & 255;
        int hoff = (k >> 6)*16384 + m*64 + ((k & 63) ^ ((m & 7) << 3));
        g_wh[hoff]              = __float2half(sw[i]);
        g_wh[Oq*Cq + hoff]      = __float2half(hw[i]);
        return;
    }
    int lane = tid & 31, warp = tid >> 5;
    int b = bc >> 8, c = bc & 255;
    int s = c >> 6, kr = c & 63;
    __shared__ float red[8][64];
    const float4* p = (const float4*)(x + (size_t)bc*TVq);
    // packed tile base for (b, s, kr): halfs
    size_t xbase = ((size_t)(b*4 + s)*64) * 8192 + (size_t)kr*128;
    int swz = (kr & 7) << 3;
    float s0=0.f, s1=0.f, s2=0.f, s3=0.f;
    int v0 = (tid*4) & 63;
    #pragma unroll
    for (int i = 0; i < 8; i++) {
        int e = tid + i*256;              // float4 index; tv0 = e*4
        float4 f = p[e];
        s0 += f.x; s1 += f.y; s2 += f.z; s3 += f.w;
        int tv0 = e*4;
        int nb = tv0 >> 7, nc = tv0 & 127;
        size_t hoff = xbase + (size_t)nb*8192 + (nc ^ swz);
        __half2 h0 = __floats2half2_rn(f.x, f.y);
        __half2 h1 = __floats2half2_rn(f.z, f.w);
        uint2 u; u.x = *(uint32_t*)&h0; u.y = *(uint32_t*)&h1;
        *(uint2*)&g_xh[hoff] = u;
    }
    s0 += __shfl_xor_sync(0xffffffffu, s0, 16);
    s1 += __shfl_xor_sync(0xffffffffu, s1, 16);
    s2 += __shfl_xor_sync(0xffffffffu, s2, 16);
    s3 += __shfl_xor_sync(0xffffffffu, s3, 16);
    if (lane < 16) {
        red[warp][v0]   = s0;
        red[warp][v0+1] = s1;
        red[warp][v0+2] = s2;
        red[warp][v0+3] = s3;
    }
    __syncthreads();
    if (tid < 64) {
        float ss = 0.f;
        #pragma unroll
        for (int w = 0; w < 8; w++) ss += red[w][tid];
        g_tp[bc*Vq + tid] = ss * (1.f/Tq);
    }
}

// x1/x2 = conv1x1(tp) — tiled
__global__ void __launch_bounds__(256) k_x1x2(const float* __restrict__ w1, const float* __restrict__ b1,
                                              const float* __restrict__ w2, const float* __restrict__ b2) {
    __shared__ float tps[64][64];
    __shared__ float w1s[16][64];
    __shared__ float w2s[16][64];
    int b = blockIdx.y, ot = blockIdx.x * 16;
    int tid = threadIdx.x;
    int v = tid & 63, og = tid >> 6;
    float a1[4] = {0.f,0.f,0.f,0.f}, a2[4] = {0.f,0.f,0.f,0.f};

    for (int c0 = 0; c0 < Cq; c0 += 64) {
        __syncthreads();
        #pragma unroll
        for (int i = 0; i < 16; i++) {
            int idx = tid + i*256;
            tps[idx >> 6][idx & 63] = g_tp[(b*Cq + c0 + (idx >> 6))*Vq + (idx & 63)];
        }
        #pragma unroll
        for (int i = 0; i < 4; i++) {
            int idx = tid + i*256;
            int o = idx >> 6, cc = idx & 63;
            w1s[o][cc] = w1[(ot + o)*Cq + c0 + cc];
            w2s[o][cc] = w2[(ot + o)*Cq + c0 + cc];
        }
        __syncthreads();
        #pragma unroll 8
        for (int cc = 0; cc < 64; cc++) {
            float t = tps[cc][v];
            #pragma unroll
            for (int j = 0; j < 4; j++) {
                a1[j] = fmaf(t, w1s[og*4 + j][cc], a1[j]);
                a2[j] = fmaf(t, w2s[og*4 + j][cc], a2[j]);
            }
        }
    }
    #pragma unroll
    for (int j = 0; j < 4; j++) {
        int o = ot + og*4 + j;
        g_x1[(b*Oq + o)*Vq + v] = a1[j] + b1[o];
        g_x2[(b*Oq + o)*Vq + v] = a2[j] + b2[o];
    }
}

// M = A_param + beta * softmax
__global__ void k_adj(const float* __restrict__ Ap, const float* __restrict__ beta_p) {
    __shared__ float x1s[32][Vq];
    __shared__ float x2s[32][Vq];
    __shared__ float S[Vq][Vq];
    __shared__ float mred[4][64];
    __shared__ float sred2[4][64];
    int bk = blockIdx.x;
    int b = bk >> 3, k = bk & 7;
    int tid = threadIdx.x;

    for (int i = tid; i < 32*Vq; i += 256) {
        int c = i >> 6, v = i & 63;
        int row = (b*Oq + k*32 + c)*Vq + v;
        x1s[c][v] = g_x1[row];
        x2s[c][v] = g_x2[row];
    }
    __syncthreads();
    for (int i = tid; i < Vq*Vq; i += 256) {
        int v = i >> 6, w = i & 63;
        float s = 0.f;
        #pragma unroll
        for (int c = 0; c < 32; c++) s = fmaf(x1s[c][v], x2s[c][w], s);
        S[v][w] = s;
    }
    __syncthreads();

    int w = tid & 63, part = tid >> 6;
    int vlo = part*16;
    float m = -1e30f;
    #pragma unroll
    for (int v = 0; v < 16; v++) m = fmaxf(m, S[vlo + v][w]);
    mred[part][w] = m;
    __syncthreads();
    m = fmaxf(fmaxf(mred[0][w], mred[1][w]), fmaxf(mred[2][w], mred[3][w]));
    float sum = 0.f;
    #pragma unroll
    for (int v = 0; v < 16; v++) {
        float e = __expf(S[vlo + v][w] - m);
        S[vlo + v][w] = e;
        sum += e;
    }
    sred2[part][w] = sum;
    __syncthreads();
    float tot = sred2[0][w] + sred2[1][w] + sred2[2][w] + sred2[3][w];
    float scl = beta_p[0] / tot;
    #pragma unroll
    for (int v = 0; v < 16; v++) {
        int vv = vlo + v;
        g_M[((bk*Vq + vv) << 6) + w] = Ap[((k*Vq + vv) << 6) + w] + S[vv][w]*scl;
    }
}

// ---------------- fp16 GEMM via TMA bulk loads of packed tiles ----------------
// smem: W stages 0..3 at s*32768 (32KB each), X stages at 131072 + s*16384 (16KB),
// mbarriers at 196608. All 4 stages loaded upfront; no ring/reuse.
#define GEMM_SMEM (196608 + 64)

__global__ void __launch_bounds__(512, 1) k_gemm(const __half* __restrict__ Wh,
                                                 const __half* __restrict__ Xg,
                                                 int part) {
    extern __shared__ __align__(128) char smraw[];
    __shared__ float sred[2][256][4];
    int b  = blockIdx.z;
    int nb = blockIdx.x;
    int n0 = nb * 128;
    int tid  = threadIdx.x;
    int warp = tid >> 5, lane = tid & 31;
    int wm = warp >> 2, wn = warp & 3;           // 4 x 4 warps, warp tile 64m x 32n
    int r  = lane >> 2, c = lane & 3;
    int l16 = lane & 15, lh = lane >> 4;

    uint32_t sbase = (uint32_t)__cvta_generic_to_shared(smraw);
    uint32_t mbar  = sbase + 196608;

    if (tid == 0) {
        #pragma unroll
        for (int s = 0; s < 4; s++) MBAR_INIT(mbar + s*8, 1);
    }
    __syncthreads();
    if (tid == 0) {
        const char* wsrc = (const char*)Wh;
        const char* xsrc = (const char*)Xg + ((size_t)(b*4)*64 + nb) * 16384;
        #pragma unroll
        for (int s = 0; s < 4; s++) {
            MBAR_EXPECT_TX(mbar + s*8, 49152);
            cpbulk(sbase + s*32768,            wsrc + (size_t)s*32768,        32768, mbar + s*8);
            cpbulk(sbase + 131072 + s*16384,   xsrc + (size_t)s*64*16384,     16384, mbar + s*8);
        }
    }

    float acc[4][4][4];
    #pragma unroll
    for (int i = 0; i < 4; i++)
        #pragma unroll
        for (int j = 0; j < 4; j++)
            #pragma unroll
            for (int q = 0; q < 4; q++) acc[i][j][q] = 0.f;

    #pragma unroll
    for (int kt = 0; kt < 4; kt++) {
        MBAR_WAIT(mbar + kt*8, 0);
        uint32_t wsb = sbase + kt*32768;
        uint32_t xsb = sbase + 131072 + kt*16384;

        #pragma unroll
        for (int ks = 0; ks < 4; ks++) {
            uint32_t Af[4][4];
            #pragma unroll
            for (int mi = 0; mi < 4; mi++) {
                int m = wm*64 + mi*16 + l16;
                uint32_t a = wsb + m*128 + (((uint32_t)(ks*32 + lh*16)) ^ (((uint32_t)(m & 7)) << 4));
                ldsm_x4(Af[mi][0], Af[mi][1], Af[mi][2], Af[mi][3], a);
            }
            uint32_t Bf[2][4];
            #pragma unroll
            for (int p = 0; p < 2; p++) {
                int k = ks*16 + l16;
                int np = wn*32 + p*16 + lh*8;
                uint32_t a = xsb + k*256 + (((uint32_t)(np*2)) ^ (((uint32_t)(k & 7)) << 4));
                ldsm_x4_t(Bf[p][0], Bf[p][1], Bf[p][2], Bf[p][3], a);
            }
            #pragma unroll
            for (int mi = 0; mi < 4; mi++)
                #pragma unroll
                for (int p = 0; p < 2; p++) {
                    mma_f16(acc[mi][2*p],   Af[mi][0], Af[mi][1], Af[mi][2], Af[mi][3],
                            Bf[p][0], Bf[p][1]);
                    mma_f16(acc[mi][2*p+1], Af[mi][0], Af[mi][1], Af[mi][2], Af[mi][3],
                            Bf[p][2], Bf[p][3]);
                }
        }
    }

    // epilogue: fp16 linear store + deterministic BN partials
    __half* Yb = g_bufAh + (size_t)b*Oq*TVq;
    #pragma unroll
    for (int mi = 0; mi < 4; mi++) {
        #pragma unroll
        for (int h = 0; h < 2; h++) {
            int row = wm*64 + mi*16 + h*8 + r;
            float s = 0.f, q = 0.f;
            #pragma unroll
            for (int ni = 0; ni < 4; ni++) {
                float v0 = acc[mi][ni][2*h], v1 = acc[mi][ni][2*h + 1];
                s += v0 + v1;
                q  = fmaf(v0, v0, fmaf(v1, v1, q));
                int col = n0 + wn*32 + ni*8 + 2*c;
                *(__half2*)&Yb[(size_t)row*TVq + col] = __floats2half2_rn(v0, v1);
            }
            s += __shfl_xor_sync(0xffffffffu, s, 1);
            s += __shfl_xor_sync(0xffffffffu, s, 2);
            q += __shfl_xor_sync(0xffffffffu, q, 1);
            q += __shfl_xor_sync(0xffffffffu, q, 2);
            if (c == 0) {
                sred[0][row][wn] = s;
                sred[1][row][wn] = q;
            }
        }
    }
    __syncthreads();
    if (tid < 256) {
        int blk = blockIdx.z*64 + blockIdx.x;
        g_psum[part][blk][tid] = (sred[0][tid][0] + sred[0][tid][1])
                               + (sred[0][tid][2] + sred[0][tid][3]);
        g_psq [part][blk][tid] = (sred[1][tid][0] + sred[1][tid][1])
                               + (sred[1][tid][2] + sred[1][tid][3]);
    }
}

// deterministic reduction of BN partials -> g_stats
__global__ void k_redstats(int part) {
    int o = blockIdx.x, tid = threadIdx.x;
    float s = 0.f, q = 0.f;
    #pragma unroll
    for (int i = 0; i < 4; i++) {
        s += g_psum[part][tid + i*256][o];
        q += g_psq [part][tid + i*256][o];
    }
    __shared__ float ss[256], qq[256];
    ss[tid] = s; qq[tid] = q;
    __syncthreads();
    for (int st = 128; st > 0; st >>= 1) {
        if (tid < st) { ss[tid] += ss[tid + st]; qq[tid] += qq[tid + st]; }
        __syncthreads();
    }
    if (tid == 0) {
        g_stats[part*2*Oq + o]      = ss[0];
        g_stats[part*2*Oq + Oq + o] = qq[0];
    }
}

// ---------------- stage5 ----------------
#define HSPh 72
#define ASPh 72
#define S5H (128*HSPh + 64*ASPh)

__global__ void __launch_bounds__(256) k_stage5(const float* __restrict__ alpha_p,
                                                const float* __restrict__ gamma,
                                                const float* __restrict__ beta) {
    extern __shared__ char smraw[];
    __half* hs = (__half*)smraw;
    __half* As = hs + 128*HSPh;

    int bx = blockIdx.x;
    int b = bx >> 8, o = bx & 255, kk = o >> 5;
    int tid  = threadIdx.x;
    int warp = tid >> 5, lane = tid & 31;
    int wm = warp >> 1, wn = warp & 1;
    int r  = lane >> 2, c = lane & 3;
    int l16 = lane & 15, lh = lane >> 4;

    float mean  = g_stats[o]      * (1.f/CNT);
    float var   = g_stats[Oq + o] * (1.f/CNT) - mean*mean;
    float scale = gamma[o] * rsqrtf(var + 1e-5f);
    float shift = beta[o] - mean*scale;

    const __half* src = g_bufAh + (size_t)bx*TVq;
    for (int i = tid; i < TVq/8; i += 256) {
        int t = (i*8) >> 6, v = (i*8) & 63;
        const __half2* s2 = (const __half2*)(src + i*8);
        __half2 out[4];
        #pragma unroll
        for (int j = 0; j < 4; j++) {
            float2 f = __half22float2(s2[j]);
            out[j] = __floats2half2_rn(fmaxf(fmaf(f.x, scale, shift), 0.f),
                                       fmaxf(fmaf(f.y, scale, shift), 0.f));
        }
        *(uint2*)&hs[t*HSPh + v]     = *(uint2*)&out[0];
        *(uint2*)&hs[t*HSPh + v + 4] = *(uint2*)&out[2];
    }

    float alpha = alpha_p[0];
    const float* x1r = g_x1 + bx*Vq;
    const float* x2r = g_x2 + bx*Vq;
    const float* Mp  = g_M + (size_t)(b*Kq + kk)*Vq*Vq;
    for (int i = tid; i < Vq*Vq; i += 256) {
        int v = i >> 6, w = i & 63;
        As[v*ASPh + w] = __float2half(Mp[i] + alpha * tanhf(x1r[v] - x2r[w]));
    }
    __syncthreads();

    uint32_t hsb = (uint32_t)__cvta_generic_to_shared(hs);
    uint32_t asb = (uint32_t)__cvta_generic_to_shared(As);

    float acc[2][4][4];
    #pragma unroll
    for (int i = 0; i < 2; i++)
        #pragma unroll
        for (int j = 0; j < 4; j++)
            #pragma unroll
            for (int q = 0; q < 4; q++) acc[i][j][q] = 0.f;

    #pragma unroll
    for (int ks = 0; ks < 4; ks++) {
        uint32_t Af[2][4];
        #pragma unroll
        for (int mi = 0; mi < 2; mi++)
            ldsm_x4(Af[mi][0], Af[mi][1], Af[mi][2], Af[mi][3],
                    hsb + ((wm*32 + mi*16 + l16)*HSPh + ks*16 + 8*lh)*2);
        uint32_t Bf[2][4];
        #pragma unroll
        for (int p = 0; p < 2; p++)
            ldsm_x4_t(Bf[p][0], Bf[p][1], Bf[p][2], Bf[p][3],
                      asb + ((ks*16 + l16)*ASPh + wn*32 + p*16 + 8*lh)*2);
        #pragma unroll
        for (int mi = 0; mi < 2; mi++)
            #pragma unroll
            for (int p = 0; p < 2; p++) {
                mma_f16(acc[mi][2*p],   Af[mi][0], Af[mi][1], Af[mi][2], Af[mi][3],
                        Bf[p][0], Bf[p][1]);
                mma_f16(acc[mi][2*p+1], Af[mi][0], Af[mi][1], Af[mi][2], Af[mi][3],
                        Bf[p][2], Bf[p][3]);
            }
    }

    // write packed+swizzled for head-GEMM TMA: s = o>>6, kr = o&63
    {
        int s = o >> 6, kr = o & 63;
        int swz = (kr & 7) << 3;
        __half* dstb = g_bufBh + ((size_t)(b*4 + s)*64) * 8192 + (size_t)kr*128;
        #pragma unroll
        for (int mi = 0; mi < 2; mi++) {
            #pragma unroll
            for (int h = 0; h < 2; h++) {
                int t = wm*32 + mi*16 + h*8 + r;
                int nb = t >> 1;
                #pragma unroll
                for (int ni = 0; ni < 4; ni++) {
                    int w = wn*32 + ni*8 + 2*c;
                    int nc = (t & 1)*64 + w;
                    size_t hoff = (size_t)nb*8192 + (nc ^ swz);
                    *(__half2*)&dstb[hoff] = __floats2half2_rn(acc[mi][ni][2*h], acc[mi][ni][2*h+1]);
                }
            }
        }
    }
}

// out = relu(BN(z) + x); z linear fp16, residual x from PACKED g_xh
__global__ void k_out(const float* __restrict__ gamma, const float* __restrict__ beta,
                      float* __restrict__ out) {
    size_t base = (size_t)blockIdx.x * 1024 + threadIdx.x;
    const __half2* zph = (const __half2*)(g_bufAh);

    __half2 z[4][2], xv[4][2];
    #pragma unroll
    for (int j = 0; j < 4; j++) {
        size_t i4 = base + j*256;
        z[j][0] = zph[i4*2];  z[j][1] = zph[i4*2 + 1];
        size_t e = i4*4;
        int bb = (int)(e >> 21);
        int cc = (int)((e >> 13) & 255);
        int tv = (int)(e & 8191);
        int s = cc >> 6, kr = cc & 63;
        int nb = tv >> 7, nc = tv & 127;
        size_t hoff = ((size_t)(bb*4 + s)*64 + nb)*8192 + kr*128 + (nc ^ ((kr & 7) << 3));
        uint2 u = *(const uint2*)&g_xh[hoff];
        xv[j][0] = *(__half2*)&u.x;
        xv[j][1] = *(__half2*)&u.y;
    }
    #pragma unroll
    for (int j = 0; j < 4; j++) {
        size_t i4 = base + j*256;
        int o = (int)((i4 >> 11) & 255);
        float mean  = g_stats[2*Oq + o] * (1.f/CNT);
        float var   = g_stats[3*Oq + o] * (1.f/CNT) - mean*mean;
        float scale = gamma[o] * rsqrtf(var + 1e-5f);
        float shift = beta[o] - mean*scale;
        float2 z0 = __half22float2(z[j][0]);
        float2 z1 = __half22float2(z[j][1]);
        float2 x0 = __half22float2(xv[j][0]);
        float2 x1 = __half22float2(xv[j][1]);
        float4 rr;
        rr.x = fmaxf(fmaf(z0.x, scale, shift) + x0.x, 0.f);
        rr.y = fmaxf(fmaf(z0.y, scale, shift) + x0.y, 0.f);
        rr.z = fmaxf(fmaf(z1.x, scale, shift) + x1.x, 0.f);
        rr.w = fmaxf(fmaf(z1.y, scale, shift) + x1.y, 0.f);
        ((float4*)out)[i4] = rr;
    }
}

// ---------------- launch ----------------
extern "C" void kernel_launch(void* const* d_in, const int* in_sizes, int n_in,
                              void* d_out, int out_size) {
    const float* x       = (const float*)d_in[0];
    const float* A_param = (const float*)d_in[1];
    const float* alpha   = (const float*)d_in[2];
    const float* beta    = (const float*)d_in[3];
    const float* w1      = (const float*)d_in[4];
    const float* b1      = (const float*)d_in[5];
    const float* w2      = (const float*)d_in[6];
    const float* b2      = (const float*)d_in[7];
    const float* stem_w  = (const float*)d_in[8];
    const float* stem_g  = (const float*)d_in[10];
    const float* stem_be = (const float*)d_in[11];
    const float* head_w  = (const float*)d_in[12];
    const float* head_g  = (const float*)d_in[14];
    const float* head_be = (const float*)d_in[15];
    float* out = (float*)d_out;

    int stage5_smem = S5H * 2;
    cudaFuncSetAttribute(k_gemm,   cudaFuncAttributeMaxDynamicSharedMemorySize, GEMM_SMEM);
    cudaFuncSetAttribute(k_stage5, cudaFuncAttributeMaxDynamicSharedMemorySize, stage5_smem);

    __half* whp = nullptr;  cudaGetSymbolAddress((void**)&whp, g_wh);
    __half* xhp = nullptr;  cudaGetSymbolAddress((void**)&xhp, g_xh);
    __half* bBp = nullptr;  cudaGetSymbolAddress((void**)&bBp, g_bufBh);

    k_meanT<<<Bq*Cq + 256, 256>>>(x, stem_w, head_w);
    k_x1x2<<<dim3(Oq/16, Bq), 256>>>(w1, b1, w2, b2);
    k_adj<<<Bq*Kq, 256>>>(A_param, beta);

    // stem conv + deterministic BN partials (bias cancels in BN)
    k_gemm<<<dim3(TVq/128, 1, Bq), 512, GEMM_SMEM>>>(whp, xhp, 0);
    k_redstats<<<Oq, 256>>>(0);

    // BN+relu + graph matmul (writes packed X for head GEMM)
    k_stage5<<<Bq*Oq, 256, stage5_smem>>>(alpha, stem_g, stem_be);

    // head conv + deterministic BN partials
    k_gemm<<<dim3(TVq/128, 1, Bq), 512, GEMM_SMEM>>>(whp + Oq*Cq, bBp, 1);
    k_redstats<<<Oq, 256>>>(1);

    k_out<<<(int)(((size_t)Bq*Oq*TVq/4)/1024), 256>>>(head_g, head_be, out);
}

// round 14
// speedup vs baseline: 1.0743x; 1.0017x over previous
#include <cuda_runtime.h>
#include <cuda_fp16.h>
#include <cmath>
#include <cstdint>

#define Bq 16
#define Cq 256
#define Tq 128
#define Vq 64
#define Kq 8
#define Oq 256
#define TVq 8192
#define CNT 131072
#define NBLK 1024            // GEMM blocks per launch = 64 * 16

// ---------------- scratch ----------------
// g_xh / g_bufBh / g_wh are stored TILE-PACKED + PRE-SWIZZLED for TMA bulk loads:
//   X (per b): [stage s=c>>6][nb=tv>>7][kr=c&63][nc^((kr&7)<<3)]  (tile = 16KB)
//   W:         [stage s=k>>6][m][ (k&63) ^ ((m&7)<<3) ]           (stage = 32KB)
__device__ float  g_tp[Bq*Cq*Vq];
__device__ float  g_x1[Bq*Oq*Vq];
__device__ float  g_x2[Bq*Oq*Vq];
__device__ float  g_M [Bq*Kq*Vq*Vq];
__device__ float  g_stats[4*Oq];
__device__ float  g_psum[2][NBLK][Oq];
__device__ float  g_psq [2][NBLK][Oq];
__device__ __align__(128) __half g_xh  [(size_t)Bq*Cq*TVq];
__device__ __align__(128) __half g_bufAh[(size_t)Bq*Oq*TVq];  // linear [b][o][tv]
__device__ __align__(128) __half g_bufBh[(size_t)Bq*Oq*TVq];  // packed (see above)
__device__ __align__(128) __half g_wh[2*Oq*Cq];               // packed per weight

// ---------------- helpers ----------------
__device__ __forceinline__ void mma_f16(float c[4],
                                        uint32_t a0, uint32_t a1, uint32_t a2, uint32_t a3,
                                        uint32_t b0, uint32_t b1) {
    asm volatile(
        "mma.sync.aligned.m16n8k16.row.col.f32.f16.f16.f32 "
        "{%0,%1,%2,%3},{%4,%5,%6,%7},{%8,%9},{%0,%1,%2,%3};\n"
        : "+f"(c[0]), "+f"(c[1]), "+f"(c[2]), "+f"(c[3])
        : "r"(a0), "r"(a1), "r"(a2), "r"(a3), "r"(b0), "r"(b1));
}
__device__ __forceinline__ void ldsm_x4(uint32_t& r0, uint32_t& r1, uint32_t& r2, uint32_t& r3,
                                        uint32_t addr) {
    asm volatile("ldmatrix.sync.aligned.m8n8.x4.shared.b16 {%0,%1,%2,%3}, [%4];\n"
                 : "=r"(r0), "=r"(r1), "=r"(r2), "=r"(r3) : "r"(addr));
}
__device__ __forceinline__ void ldsm_x4_t(uint32_t& r0, uint32_t& r1, uint32_t& r2, uint32_t& r3,
                                          uint32_t addr) {
    asm volatile("ldmatrix.sync.aligned.m8n8.x4.trans.shared.b16 {%0,%1,%2,%3}, [%4];\n"
                 : "=r"(r0), "=r"(r1), "=r"(r2), "=r"(r3) : "r"(addr));
}
__device__ __forceinline__ void cpbulk(uint32_t dst, const void* src, uint32_t bytes, uint32_t mbar) {
    asm volatile("cp.async.bulk.shared::cta.global.mbarrier::complete_tx::bytes [%0], [%1], %2, [%3];\n"
                 :: "r"(dst), "l"(src), "r"(bytes), "r"(mbar) : "memory");
}
#define MBAR_INIT(addr, cnt) \
    asm volatile("mbarrier.init.shared.b64 [%0], %1;" :: "r"(addr), "r"(cnt) : "memory")
#define MBAR_EXPECT_TX(addr, bytes) \
    asm volatile("mbarrier.arrive.expect_tx.shared.b64 _, [%0], %1;" :: "r"(addr), "r"(bytes) : "memory")
#define MBAR_WAIT(addr, parity) do {                                                   \
    uint32_t _m = (addr), _p = (parity), _d;                                           \
    asm volatile("{\n\t.reg .pred p;\n\t"                                              \
        "mbarrier.try_wait.parity.acquire.cta.shared::cta.b64 p, [%1], %2;\n\t"        \
        "selp.b32 %0, 1, 0, p;\n\t}" : "=r"(_d) : "r"(_m), "r"(_p) : "memory");        \
    if (!_d) {                                                                         \
        asm volatile("{\n\t.reg .pred P1;\n\t"                                         \
            "WL_%=:\n\t"                                                               \
            "mbarrier.try_wait.parity.acquire.cta.shared::cta.b64 P1, [%0], %1, 0x989680;\n\t" \
            "@P1 bra.uni WD_%=;\n\t"                                                   \
            "bra.uni WL_%=;\n\t"                                                       \
            "WD_%=:\n\t}" :: "r"(_m), "r"(_p) : "memory");                             \
    }                                                                                  \
} while (0)

// x -> packed/swizzled fp16 copy + per-(b,c) mean over T; extra blocks pack weights
__global__ void k_meanT(const float* __restrict__ x,
                        const float* __restrict__ sw, const float* __restrict__ hw) {
    int bc = blockIdx.x;
    int tid = threadIdx.x;
    if (bc >= Bq*Cq) {                    // weight-packing blocks
        int i = (bc - Bq*Cq)*256 + tid;   // i = m*256 + k  over 65536
        int m = i >> 8, k = i & 255;
        int hoff = (k >> 6)*16384 + m*64 + ((k & 63) ^ ((m & 7) << 3));
        g_wh[hoff]              = __float2half(sw[i]);
        g_wh[Oq*Cq + hoff]      = __float2half(hw[i]);
        return;
    }
    int lane = tid & 31, warp = tid >> 5;
    int b = bc >> 8, c = bc & 255;
    int s = c >> 6, kr = c & 63;
    __shared__ float red[8][64];
    const float4* p = (const float4*)(x + (size_t)bc*TVq);
    // packed tile base for (b, s, kr): halfs
    size_t xbase = ((size_t)(b*4 + s)*64) * 8192 + (size_t)kr*128;
    int swz = (kr & 7) << 3;
    float s0=0.f, s1=0.f, s2=0.f, s3=0.f;
    int v0 = (tid*4) & 63;
    #pragma unroll
    for (int i = 0; i < 8; i++) {
        int e = tid + i*256;              // float4 index; tv0 = e*4
        float4 f = p[e];
        s0 += f.x; s1 += f.y; s2 += f.z; s3 += f.w;
        int tv0 = e*4;
        int nb = tv0 >> 7, nc = tv0 & 127;
        size_t hoff = xbase + (size_t)nb*8192 + (nc ^ swz);
        __half2 h0 = __floats2half2_rn(f.x, f.y);
        __half2 h1 = __floats2half2_rn(f.z, f.w);
        uint2 u; u.x = *(uint32_t*)&h0; u.y = *(uint32_t*)&h1;
        *(uint2*)&g_xh[hoff] = u;
    }
    s0 += __shfl_xor_sync(0xffffffffu, s0, 16);
    s1 += __shfl_xor_sync(0xffffffffu, s1, 16);
    s2 += __shfl_xor_sync(0xffffffffu, s2, 16);
    s3 += __shfl_xor_sync(0xffffffffu, s3, 16);
    if (lane < 16) {
        red[warp][v0]   = s0;
        red[warp][v0+1] = s1;
        red[warp][v0+2] = s2;
        red[warp][v0+3] = s3;
    }
    __syncthreads();
    if (tid < 64) {
        float ss = 0.f;
        #pragma unroll
        for (int w = 0; w < 8; w++) ss += red[w][tid];
        g_tp[bc*Vq + tid] = ss * (1.f/Tq);
    }
}

// x1/x2 = conv1x1(tp) — tiled
__global__ void __launch_bounds__(256) k_x1x2(const float* __restrict__ w1, const float* __restrict__ b1,
                                              const float* __restrict__ w2, const float* __restrict__ b2) {
    __shared__ float tps[64][64];
    __shared__ float w1s[16][64];
    __shared__ float w2s[16][64];
    int b = blockIdx.y, ot = blockIdx.x * 16;
    int tid = threadIdx.x;
    int v = tid & 63, og = tid >> 6;
    float a1[4] = {0.f,0.f,0.f,0.f}, a2[4] = {0.f,0.f,0.f,0.f};

    for (int c0 = 0; c0 < Cq; c0 += 64) {
        __syncthreads();
        #pragma unroll
        for (int i = 0; i < 16; i++) {
            int idx = tid + i*256;
            tps[idx >> 6][idx & 63] = g_tp[(b*Cq + c0 + (idx >> 6))*Vq + (idx & 63)];
        }
        #pragma unroll
        for (int i = 0; i < 4; i++) {
            int idx = tid + i*256;
            int o = idx >> 6, cc = idx & 63;
            w1s[o][cc] = w1[(ot + o)*Cq + c0 + cc];
            w2s[o][cc] = w2[(ot + o)*Cq + c0 + cc];
        }
        __syncthreads();
        #pragma unroll 8
        for (int cc = 0; cc < 64; cc++) {
            float t = tps[cc][v];
            #pragma unroll
            for (int j = 0; j < 4; j++) {
                a1[j] = fmaf(t, w1s[og*4 + j][cc], a1[j]);
                a2[j] = fmaf(t, w2s[og*4 + j][cc], a2[j]);
            }
        }
    }
    #pragma unroll
    for (int j = 0; j < 4; j++) {
        int o = ot + og*4 + j;
        g_x1[(b*Oq + o)*Vq + v] = a1[j] + b1[o];
        g_x2[(b*Oq + o)*Vq + v] = a2[j] + b2[o];
    }
}

// M = A_param + beta * softmax
__global__ void k_adj(const float* __restrict__ Ap, const float* __restrict__ beta_p) {
    __shared__ float x1s[32][Vq];
    __shared__ float x2s[32][Vq];
    __shared__ float S[Vq][Vq];
    __shared__ float mred[4][64];
    __shared__ float sred2[4][64];
    int bk = blockIdx.x;
    int b = bk >> 3, k = bk & 7;
    int tid = threadIdx.x;

    for (int i = tid; i < 32*Vq; i += 256) {
        int c = i >> 6, v = i & 63;
        int row = (b*Oq + k*32 + c)*Vq + v;
        x1s[c][v] = g_x1[row];
        x2s[c][v] = g_x2[row];
    }
    __syncthreads();
    for (int i = tid; i < Vq*Vq; i += 256) {
        int v = i >> 6, w = i & 63;
        float s = 0.f;
        #pragma unroll
        for (int c = 0; c < 32; c++) s = fmaf(x1s[c][v], x2s[c][w], s);
        S[v][w] = s;
    }
    __syncthreads();

    int w = tid & 63, part = tid >> 6;
    int vlo = part*16;
    float m = -1e30f;
    #pragma unroll
    for (int v = 0; v < 16; v++) m = fmaxf(m, S[vlo + v][w]);
    mred[part][w] = m;
    __syncthreads();
    m = fmaxf(fmaxf(mred[0][w], mred[1][w]), fmaxf(mred[2][w], mred[3][w]));
    float sum = 0.f;
    #pragma unroll
    for (int v = 0; v < 16; v++) {
        float e = __expf(S[vlo + v][w] - m);
        S[vlo + v][w] = e;
        sum += e;
    }
    sred2[part][w] = sum;
    __syncthreads();
    float tot = sred2[0][w] + sred2[1][w] + sred2[2][w] + sred2[3][w];
    float scl = beta_p[0] / tot;
    #pragma unroll
    for (int v = 0; v < 16; v++) {
        int vv = vlo + v;
        g_M[((bk*Vq + vv) << 6) + w] = Ap[((k*Vq + vv) << 6) + w] + S[vv][w]*scl;
    }
}

// ---------------- fp16 GEMM via TMA bulk loads of packed tiles ----------------
// smem: W stages 0..3 at s*32768 (32KB each), X stages at 131072 + s*16384 (16KB),
// mbarriers at 196608. All 4 stages loaded upfront; no ring/reuse.
#define GEMM_SMEM (196608 + 64)

__global__ void __launch_bounds__(512, 1) k_gemm(const __half* __restrict__ Wh,
                                                 const __half* __restrict__ Xg,
                                                 int part) {
    extern __shared__ __align__(128) char smraw[];
    __shared__ float sred[2][256][4];
    int b  = blockIdx.z;
    int nb = blockIdx.x;
    int n0 = nb * 128;
    int tid  = threadIdx.x;
    int warp = tid >> 5, lane = tid & 31;
    int wm = warp >> 2, wn = warp & 3;           // 4 x 4 warps, warp tile 64m x 32n
    int r  = lane >> 2, c = lane & 3;
    int l16 = lane & 15, lh = lane >> 4;

    uint32_t sbase = (uint32_t)__cvta_generic_to_shared(smraw);
    uint32_t mbar  = sbase + 196608;

    if (tid == 0) {
        #pragma unroll
        for (int s = 0; s < 4; s++) MBAR_INIT(mbar + s*8, 1);
    }
    __syncthreads();
    if (tid == 0) {
        const char* wsrc = (const char*)Wh;
        const char* xsrc = (const char*)Xg + ((size_t)(b*4)*64 + nb) * 16384;
        #pragma unroll
        for (int s = 0; s < 4; s++) {
            MBAR_EXPECT_TX(mbar + s*8, 49152);
            cpbulk(sbase + s*32768,            wsrc + (size_t)s*32768,        32768, mbar + s*8);
            cpbulk(sbase + 131072 + s*16384,   xsrc + (size_t)s*64*16384,     16384, mbar + s*8);
        }
    }

    float acc[4][4][4];
    #pragma unroll
    for (int i = 0; i < 4; i++)
        #pragma unroll
        for (int j = 0; j < 4; j++)
            #pragma unroll
            for (int q = 0; q < 4; q++) acc[i][j][q] = 0.f;

    #pragma unroll
    for (int kt = 0; kt < 4; kt++) {
        MBAR_WAIT(mbar + kt*8, 0);
        uint32_t wsb = sbase + kt*32768;
        uint32_t xsb = sbase + 131072 + kt*16384;

        #pragma unroll
        for (int ks = 0; ks < 4; ks++) {
            uint32_t Af[4][4];
            #pragma unroll
            for (int mi = 0; mi < 4; mi++) {
                int m = wm*64 + mi*16 + l16;
                uint32_t a = wsb + m*128 + (((uint32_t)(ks*32 + lh*16)) ^ (((uint32_t)(m & 7)) << 4));
                ldsm_x4(Af[mi][0], Af[mi][1], Af[mi][2], Af[mi][3], a);
            }
            uint32_t Bf[2][4];
            #pragma unroll
            for (int p = 0; p < 2; p++) {
                int k = ks*16 + l16;
                int np = wn*32 + p*16 + lh*8;
                uint32_t a = xsb + k*256 + (((uint32_t)(np*2)) ^ (((uint32_t)(k & 7)) << 4));
                ldsm_x4_t(Bf[p][0], Bf[p][1], Bf[p][2], Bf[p][3], a);
            }
            #pragma unroll
            for (int mi = 0; mi < 4; mi++)
                #pragma unroll
                for (int p = 0; p < 2; p++) {
                    mma_f16(acc[mi][2*p],   Af[mi][0], Af[mi][1], Af[mi][2], Af[mi][3],
                            Bf[p][0], Bf[p][1]);
                    mma_f16(acc[mi][2*p+1], Af[mi][0], Af[mi][1], Af[mi][2], Af[mi][3],
                            Bf[p][2], Bf[p][3]);
                }
        }
    }

    // epilogue: fp16 linear store + deterministic BN partials
    __half* Yb = g_bufAh + (size_t)b*Oq*TVq;
    #pragma unroll
    for (int mi = 0; mi < 4; mi++) {
        #pragma unroll
        for (int h = 0; h < 2; h++) {
            int row = wm*64 + mi*16 + h*8 + r;
            float s = 0.f, q = 0.f;
            #pragma unroll
            for (int ni = 0; ni < 4; ni++) {
                float v0 = acc[mi][ni][2*h], v1 = acc[mi][ni][2*h + 1];
                s += v0 + v1;
                q  = fmaf(v0, v0, fmaf(v1, v1, q));
                int col = n0 + wn*32 + ni*8 + 2*c;
                *(__half2*)&Yb[(size_t)row*TVq + col] = __floats2half2_rn(v0, v1);
            }
            s += __shfl_xor_sync(0xffffffffu, s, 1);
            s += __shfl_xor_sync(0xffffffffu, s, 2);
            q += __shfl_xor_sync(0xffffffffu, q, 1);
            q += __shfl_xor_sync(0xffffffffu, q, 2);
            if (c == 0) {
                sred[0][row][wn] = s;
                sred[1][row][wn] = q;
            }
        }
    }
    __syncthreads();
    if (tid < 256) {
        int blk = blockIdx.z*64 + blockIdx.x;
        g_psum[part][blk][tid] = (sred[0][tid][0] + sred[0][tid][1])
                               + (sred[0][tid][2] + sred[0][tid][3]);
        g_psq [part][blk][tid] = (sred[1][tid][0] + sred[1][tid][1])
                               + (sred[1][tid][2] + sred[1][tid][3]);
    }
}

// deterministic reduction of BN partials -> g_stats
__global__ void k_redstats(int part) {
    int o = blockIdx.x, tid = threadIdx.x;
    float s = 0.f, q = 0.f;
    #pragma unroll
    for (int i = 0; i < 4; i++) {
        s += g_psum[part][tid + i*256][o];
        q += g_psq [part][tid + i*256][o];
    }
    __shared__ float ss[256], qq[256];
    ss[tid] = s; qq[tid] = q;
    __syncthreads();
    for (int st = 128; st > 0; st >>= 1) {
        if (tid < st) { ss[tid] += ss[tid + st]; qq[tid] += qq[tid + st]; }
        __syncthreads();
    }
    if (tid == 0) {
        g_stats[part*2*Oq + o]      = ss[0];
        g_stats[part*2*Oq + Oq + o] = qq[0];
    }
}

// ---------------- stage5 ----------------
#define HSPh 72
#define ASPh 72
#define S5H (128*HSPh + 64*ASPh)

__global__ void __launch_bounds__(256) k_stage5(const float* __restrict__ alpha_p,
                                                const float* __restrict__ gamma,
                                                const float* __restrict__ beta) {
    extern __shared__ char smraw[];
    __half* hs = (__half*)smraw;
    __half* As = hs + 128*HSPh;

    int bx = blockIdx.x;
    int b = bx >> 8, o = bx & 255, kk = o >> 5;
    int tid  = threadIdx.x;
    int warp = tid >> 5, lane = tid & 31;
    int wm = warp >> 1, wn = warp & 1;
    int r  = lane >> 2, c = lane & 3;
    int l16 = lane & 15, lh = lane >> 4;

    float mean  = g_stats[o]      * (1.f/CNT);
    float var   = g_stats[Oq + o] * (1.f/CNT) - mean*mean;
    float scale = gamma[o] * rsqrtf(var + 1e-5f);
    float shift = beta[o] - mean*scale;

    const __half* src = g_bufAh + (size_t)bx*TVq;
    for (int i = tid; i < TVq/8; i += 256) {
        int t = (i*8) >> 6, v = (i*8) & 63;
        const __half2* s2 = (const __half2*)(src + i*8);
        __half2 out[4];
        #pragma unroll
        for (int j = 0; j < 4; j++) {
            float2 f = __half22float2(s2[j]);
            out[j] = __floats2half2_rn(fmaxf(fmaf(f.x, scale, shift), 0.f),
                                       fmaxf(fmaf(f.y, scale, shift), 0.f));
        }
        *(uint2*)&hs[t*HSPh + v]     = *(uint2*)&out[0];
        *(uint2*)&hs[t*HSPh + v + 4] = *(uint2*)&out[2];
    }

    float alpha = alpha_p[0];
    const float* x1r = g_x1 + bx*Vq;
    const float* x2r = g_x2 + bx*Vq;
    const float* Mp  = g_M + (size_t)(b*Kq + kk)*Vq*Vq;
    for (int i = tid; i < Vq*Vq; i += 256) {
        int v = i >> 6, w = i & 63;
        As[v*ASPh + w] = __float2half(Mp[i] + alpha * tanhf(x1r[v] - x2r[w]));
    }
    __syncthreads();

    uint32_t hsb = (uint32_t)__cvta_generic_to_shared(hs);
    uint32_t asb = (uint32_t)__cvta_generic_to_shared(As);

    float acc[2][4][4];
    #pragma unroll
    for (int i = 0; i < 2; i++)
        #pragma unroll
        for (int j = 0; j < 4; j++)
            #pragma unroll
            for (int q = 0; q < 4; q++) acc[i][j][q] = 0.f;

    #pragma unroll
    for (int ks = 0; ks < 4; ks++) {
        uint32_t Af[2][4];
        #pragma unroll
        for (int mi = 0; mi < 2; mi++)
            ldsm_x4(Af[mi][0], Af[mi][1], Af[mi][2], Af[mi][3],
                    hsb + ((wm*32 + mi*16 + l16)*HSPh + ks*16 + 8*lh)*2);
        uint32_t Bf[2][4];
        #pragma unroll
        for (int p = 0; p < 2; p++)
            ldsm_x4_t(Bf[p][0], Bf[p][1], Bf[p][2], Bf[p][3],
                      asb + ((ks*16 + l16)*ASPh + wn*32 + p*16 + 8*lh)*2);
        #pragma unroll
        for (int mi = 0; mi < 2; mi++)
            #pragma unroll
            for (int p = 0; p < 2; p++) {
                mma_f16(acc[mi][2*p],   Af[mi][0], Af[mi][1], Af[mi][2], Af[mi][3],
                        Bf[p][0], Bf[p][1]);
                mma_f16(acc[mi][2*p+1], Af[mi][0], Af[mi][1], Af[mi][2], Af[mi][3],
                        Bf[p][2], Bf[p][3]);
            }
    }

    // write packed+swizzled for head-GEMM TMA: s = o>>6, kr = o&63
    {
        int s = o >> 6, kr = o & 63;
        int swz = (kr & 7) << 3;
        __half* dstb = g_bufBh + ((size_t)(b*4 + s)*64) * 8192 + (size_t)kr*128;
        #pragma unroll
        for (int mi = 0; mi < 2; mi++) {
            #pragma unroll
            for (int h = 0; h < 2; h++) {
                int t = wm*32 + mi*16 + h*8 + r;
                int nb = t >> 1;
                #pragma unroll
                for (int ni = 0; ni < 4; ni++) {
                    int w = wn*32 + ni*8 + 2*c;
                    int nc = (t & 1)*64 + w;
                    size_t hoff = (size_t)nb*8192 + (nc ^ swz);
                    *(__half2*)&dstb[hoff] = __floats2half2_rn(acc[mi][ni][2*h], acc[mi][ni][2*h+1]);
                }
            }
        }
    }
}

// out = relu(BN(z) + x); z linear fp16, residual x from PACKED g_xh
__global__ void k_out(const float* __restrict__ gamma, const float* __restrict__ beta,
                      float* __restrict__ out) {
    size_t base = (size_t)blockIdx.x * 1024 + threadIdx.x;
    const __half2* zph = (const __half2*)(g_bufAh);

    __half2 z[4][2], xv[4][2];
    #pragma unroll
    for (int j = 0; j < 4; j++) {
        size_t i4 = base + j*256;
        z[j][0] = zph[i4*2];  z[j][1] = zph[i4*2 + 1];
        size_t e = i4*4;
        int bb = (int)(e >> 21);
        int cc = (int)((e >> 13) & 255);
        int tv = (int)(e & 8191);
        int s = cc >> 6, kr = cc & 63;
        int nb = tv >> 7, nc = tv & 127;
        size_t hoff = ((size_t)(bb*4 + s)*64 + nb)*8192 + kr*128 + (nc ^ ((kr & 7) << 3));
        uint2 u = *(const uint2*)&g_xh[hoff];
        xv[j][0] = *(__half2*)&u.x;
        xv[j][1] = *(__half2*)&u.y;
    }
    #pragma unroll
    for (int j = 0; j < 4; j++) {
        size_t i4 = base + j*256;
        int o = (int)((i4 >> 11) & 255);
        float mean  = g_stats[2*Oq + o] * (1.f/CNT);
        float var   = g_stats[3*Oq + o] * (1.f/CNT) - mean*mean;
        float scale = gamma[o] * rsqrtf(var + 1e-5f);
        float shift = beta[o] - mean*scale;
        float2 z0 = __half22float2(z[j][0]);
        float2 z1 = __half22float2(z[j][1]);
        float2 x0 = __half22float2(xv[j][0]);
        float2 x1 = __half22float2(xv[j][1]);
        float4 rr;
        rr.x = fmaxf(fmaf(z0.x, scale, shift) + x0.x, 0.f);
        rr.y = fmaxf(fmaf(z0.y, scale, shift) + x0.y, 0.f);
        rr.z = fmaxf(fmaf(z1.x, scale, shift) + x1.x, 0.f);
        rr.w = fmaxf(fmaf(z1.y, scale, shift) + x1.y, 0.f);
        ((float4*)out)[i4] = rr;
    }
}

// ---------------- launch ----------------
extern "C" void kernel_launch(void* const* d_in, const int* in_sizes, int n_in,
                              void* d_out, int out_size) {
    const float* x       = (const float*)d_in[0];
    const float* A_param = (const float*)d_in[1];
    const float* alpha   = (const float*)d_in[2];
    const float* beta    = (const float*)d_in[3];
    const float* w1      = (const float*)d_in[4];
    const float* b1      = (const float*)d_in[5];
    const float* w2      = (const float*)d_in[6];
    const float* b2      = (const float*)d_in[7];
    const float* stem_w  = (const float*)d_in[8];
    const float* stem_g  = (const float*)d_in[10];
    const float* stem_be = (const float*)d_in[11];
    const float* head_w  = (const float*)d_in[12];
    const float* head_g  = (const float*)d_in[14];
    const float* head_be = (const float*)d_in[15];
    float* out = (float*)d_out;

    int stage5_smem = S5H * 2;
    cudaFuncSetAttribute(k_gemm,   cudaFuncAttributeMaxDynamicSharedMemorySize, GEMM_SMEM);
    cudaFuncSetAttribute(k_stage5, cudaFuncAttributeMaxDynamicSharedMemorySize, stage5_smem);

    __half* whp = nullptr;  cudaGetSymbolAddress((void**)&whp, g_wh);
    __half* xhp = nullptr;  cudaGetSymbolAddress((void**)&xhp, g_xh);
    __half* bBp = nullptr;  cudaGetSymbolAddress((void**)&bBp, g_bufBh);

    k_meanT<<<Bq*Cq + 256, 256>>>(x, stem_w, head_w);
    k_x1x2<<<dim3(Oq/16, Bq), 256>>>(w1, b1, w2, b2);
    k_adj<<<Bq*Kq, 256>>>(A_param, beta);

    // stem conv + deterministic BN partials (bias cancels in BN)
    k_gemm<<<dim3(TVq/128, 1, Bq), 512, GEMM_SMEM>>>(whp, xhp, 0);
    k_redstats<<<Oq, 256>>>(0);

    // BN+relu + graph matmul (writes packed X for head GEMM)
    k_stage5<<<Bq*Oq, 256, stage5_smem>>>(alpha, stem_g, stem_be);

    // head conv + deterministic BN partials
    k_gemm<<<dim3(TVq/128, 1, Bq), 512, GEMM_SMEM>>>(whp + Oq*Cq, bBp, 1);
    k_redstats<<<Oq, 256>>>(1);

    k_out<<<(int)(((size_t)Bq*Oq*TVq/4)/1024), 256>>>(head_g, head_be, out);
}

// round 15
// speedup vs baseline: 1.0761x; 1.0017x over previous
#include <cuda_runtime.h>
#include <cuda_fp16.h>
#include <cmath>
#include <cstdint>

#define Bq 16
#define Cq 256
#define Tq 128
#define Vq 64
#define Kq 8
#define Oq 256
#define TVq 8192
#define CNT 131072
#define NBLK 1024            // GEMM blocks per launch = 64 * 16

// ---------------- scratch ----------------
// g_xh / g_bufBh / g_wh are stored TILE-PACKED + PRE-SWIZZLED for TMA bulk loads:
//   X (per b): [stage s=c>>6][nb=tv>>7][kr=c&63][nc^((kr&7)<<3)]  (tile = 16KB)
//   W:         [stage s=k>>6][m][ (k&63) ^ ((m&7)<<3) ]           (stage = 32KB)
__device__ float  g_tp[Bq*Cq*Vq];
__device__ float  g_x1[Bq*Oq*Vq];
__device__ float  g_x2[Bq*Oq*Vq];
__device__ float  g_M [Bq*Kq*Vq*Vq];
__device__ float  g_stats[4*Oq];
__device__ float  g_psum[2][NBLK][Oq];
__device__ float  g_psq [2][NBLK][Oq];
__device__ __align__(128) __half g_xh  [(size_t)Bq*Cq*TVq];
__device__ __align__(128) __half g_bufAh[(size_t)Bq*Oq*TVq];  // linear [b][o][tv]
__device__ __align__(128) __half g_bufBh[(size_t)Bq*Oq*TVq];  // packed (see above)
__device__ __align__(128) __half g_wh[2*Oq*Cq];               // packed per weight

// ---------------- helpers ----------------
__device__ __forceinline__ void mma_f16(float c[4],
                                        uint32_t a0, uint32_t a1, uint32_t a2, uint32_t a3,
                                        uint32_t b0, uint32_t b1) {
    asm volatile(
        "mma.sync.aligned.m16n8k16.row.col.f32.f16.f16.f32 "
        "{%0,%1,%2,%3},{%4,%5,%6,%7},{%8,%9},{%0,%1,%2,%3};\n"
        : "+f"(c[0]), "+f"(c[1]), "+f"(c[2]), "+f"(c[3])
        : "r"(a0), "r"(a1), "r"(a2), "r"(a3), "r"(b0), "r"(b1));
}
__device__ __forceinline__ void ldsm_x4(uint32_t& r0, uint32_t& r1, uint32_t& r2, uint32_t& r3,
                                        uint32_t addr) {
    asm volatile("ldmatrix.sync.aligned.m8n8.x4.shared.b16 {%0,%1,%2,%3}, [%4];\n"
                 : "=r"(r0), "=r"(r1), "=r"(r2), "=r"(r3) : "r"(addr));
}
__device__ __forceinline__ void ldsm_x4_t(uint32_t& r0, uint32_t& r1, uint32_t& r2, uint32_t& r3,
                                          uint32_t addr) {
    asm volatile("ldmatrix.sync.aligned.m8n8.x4.trans.shared.b16 {%0,%1,%2,%3}, [%4];\n"
                 : "=r"(r0), "=r"(r1), "=r"(r2), "=r"(r3) : "r"(addr));
}
__device__ __forceinline__ void cpbulk(uint32_t dst, const void* src, uint32_t bytes, uint32_t mbar) {
    asm volatile("cp.async.bulk.shared::cta.global.mbarrier::complete_tx::bytes [%0], [%1], %2, [%3];\n"
                 :: "r"(dst), "l"(src), "r"(bytes), "r"(mbar) : "memory");
}
#define MBAR_INIT(addr, cnt) \
    asm volatile("mbarrier.init.shared.b64 [%0], %1;" :: "r"(addr), "r"(cnt) : "memory")
#define MBAR_EXPECT_TX(addr, bytes) \
    asm volatile("mbarrier.arrive.expect_tx.shared.b64 _, [%0], %1;" :: "r"(addr), "r"(bytes) : "memory")
#define MBAR_WAIT(addr, parity) do {                                                   \
    uint32_t _m = (addr), _p = (parity), _d;                                           \
    asm volatile("{\n\t.reg .pred p;\n\t"                                              \
        "mbarrier.try_wait.parity.acquire.cta.shared::cta.b64 p, [%1], %2;\n\t"        \
        "selp.b32 %0, 1, 0, p;\n\t}" : "=r"(_d) : "r"(_m), "r"(_p) : "memory");        \
    if (!_d) {                                                                         \
        asm volatile("{\n\t.reg .pred P1;\n\t"                                         \
            "WL_%=:\n\t"                                                               \
            "mbarrier.try_wait.parity.acquire.cta.shared::cta.b64 P1, [%0], %1, 0x989680;\n\t" \
            "@P1 bra.uni WD_%=;\n\t"                                                   \
            "bra.uni WL_%=;\n\t"                                                       \
            "WD_%=:\n\t}" :: "r"(_m), "r"(_p) : "memory");                             \
    }                                                                                  \
} while (0)

// x -> packed/swizzled fp16 copy + per-(b,c) mean over T; extra blocks pack weights
__global__ void k_meanT(const float* __restrict__ x,
                        const float* __restrict__ sw, const float* __restrict__ hw) {
    int bc = blockIdx.x;
    int tid = threadIdx.x;
    if (bc >= Bq*Cq) {                    // weight-packing blocks
        int i = (bc - Bq*Cq)*256 + tid;   // i = m*256 + k  over 65536
        int m = i >> 8, k = i & 255;
        int hoff = (k >> 6)*16384 + m*64 + ((k & 63) ^ ((m & 7) << 3));
        g_wh[hoff]              = __float2half(sw[i]);
        g_wh[Oq*Cq + hoff]      = __float2half(hw[i]);
        return;
    }
    int lane = tid & 31, warp = tid >> 5;
    int b = bc >> 8, c = bc & 255;
    int s = c >> 6, kr = c & 63;
    __shared__ float red[8][64];
    const float4* p = (const float4*)(x + (size_t)bc*TVq);
    // packed tile base for (b, s, kr): halfs
    size_t xbase = ((size_t)(b*4 + s)*64) * 8192 + (size_t)kr*128;
    int swz = (kr & 7) << 3;
    float s0=0.f, s1=0.f, s2=0.f, s3=0.f;
    int v0 = (tid*4) & 63;
    #pragma unroll
    for (int i = 0; i < 8; i++) {
        int e = tid + i*256;              // float4 index; tv0 = e*4
        float4 f = p[e];
        s0 += f.x; s1 += f.y; s2 += f.z; s3 += f.w;
        int tv0 = e*4;
        int nb = tv0 >> 7, nc = tv0 & 127;
        size_t hoff = xbase + (size_t)nb*8192 + (nc ^ swz);
        __half2 h0 = __floats2half2_rn(f.x, f.y);
        __half2 h1 = __floats2half2_rn(f.z, f.w);
        uint2 u; u.x = *(uint32_t*)&h0; u.y = *(uint32_t*)&h1;
        *(uint2*)&g_xh[hoff] = u;
    }
    s0 += __shfl_xor_sync(0xffffffffu, s0, 16);
    s1 += __shfl_xor_sync(0xffffffffu, s1, 16);
    s2 += __shfl_xor_sync(0xffffffffu, s2, 16);
    s3 += __shfl_xor_sync(0xffffffffu, s3, 16);
    if (lane < 16) {
        red[warp][v0]   = s0;
        red[warp][v0+1] = s1;
        red[warp][v0+2] = s2;
        red[warp][v0+3] = s3;
    }
    __syncthreads();
    if (tid < 64) {
        float ss = 0.f;
        #pragma unroll
        for (int w = 0; w < 8; w++) ss += red[w][tid];
        g_tp[bc*Vq + tid] = ss * (1.f/Tq);
    }
}

// x1/x2 = conv1x1(tp) — tiled
__global__ void __launch_bounds__(256) k_x1x2(const float* __restrict__ w1, const float* __restrict__ b1,
                                              const float* __restrict__ w2, const float* __restrict__ b2) {
    __shared__ float tps[64][64];
    __shared__ float w1s[16][64];
    __shared__ float w2s[16][64];
    int b = blockIdx.y, ot = blockIdx.x * 16;
    int tid = threadIdx.x;
    int v = tid & 63, og = tid >> 6;
    float a1[4] = {0.f,0.f,0.f,0.f}, a2[4] = {0.f,0.f,0.f,0.f};

    for (int c0 = 0; c0 < Cq; c0 += 64) {
        __syncthreads();
        #pragma unroll
        for (int i = 0; i < 16; i++) {
            int idx = tid + i*256;
            tps[idx >> 6][idx & 63] = g_tp[(b*Cq + c0 + (idx >> 6))*Vq + (idx & 63)];
        }
        #pragma unroll
        for (int i = 0; i < 4; i++) {
            int idx = tid + i*256;
            int o = idx >> 6, cc = idx & 63;
            w1s[o][cc] = w1[(ot + o)*Cq + c0 + cc];
            w2s[o][cc] = w2[(ot + o)*Cq + c0 + cc];
        }
        __syncthreads();
        #pragma unroll 8
        for (int cc = 0; cc < 64; cc++) {
            float t = tps[cc][v];
            #pragma unroll
            for (int j = 0; j < 4; j++) {
                a1[j] = fmaf(t, w1s[og*4 + j][cc], a1[j]);
                a2[j] = fmaf(t, w2s[og*4 + j][cc], a2[j]);
            }
        }
    }
    #pragma unroll
    for (int j = 0; j < 4; j++) {
        int o = ot + og*4 + j;
        g_x1[(b*Oq + o)*Vq + v] = a1[j] + b1[o];
        g_x2[(b*Oq + o)*Vq + v] = a2[j] + b2[o];
    }
}

// M = A_param + beta * softmax
__global__ void k_adj(const float* __restrict__ Ap, const float* __restrict__ beta_p) {
    __shared__ float x1s[32][Vq];
    __shared__ float x2s[32][Vq];
    __shared__ float S[Vq][Vq];
    __shared__ float mred[4][64];
    __shared__ float sred2[4][64];
    int bk = blockIdx.x;
    int b = bk >> 3, k = bk & 7;
    int tid = threadIdx.x;

    for (int i = tid; i < 32*Vq; i += 256) {
        int c = i >> 6, v = i & 63;
        int row = (b*Oq + k*32 + c)*Vq + v;
        x1s[c][v] = g_x1[row];
        x2s[c][v] = g_x2[row];
    }
    __syncthreads();
    for (int i = tid; i < Vq*Vq; i += 256) {
        int v = i >> 6, w = i & 63;
        float s = 0.f;
        #pragma unroll
        for (int c = 0; c < 32; c++) s = fmaf(x1s[c][v], x2s[c][w], s);
        S[v][w] = s;
    }
    __syncthreads();

    int w = tid & 63, part = tid >> 6;
    int vlo = part*16;
    float m = -1e30f;
    #pragma unroll
    for (int v = 0; v < 16; v++) m = fmaxf(m, S[vlo + v][w]);
    mred[part][w] = m;
    __syncthreads();
    m = fmaxf(fmaxf(mred[0][w], mred[1][w]), fmaxf(mred[2][w], mred[3][w]));
    float sum = 0.f;
    #pragma unroll
    for (int v = 0; v < 16; v++) {
        float e = __expf(S[vlo + v][w] - m);
        S[vlo + v][w] = e;
        sum += e;
    }
    sred2[part][w] = sum;
    __syncthreads();
    float tot = sred2[0][w] + sred2[1][w] + sred2[2][w] + sred2[3][w];
    float scl = beta_p[0] / tot;
    #pragma unroll
    for (int v = 0; v < 16; v++) {
        int vv = vlo + v;
        g_M[((bk*Vq + vv) << 6) + w] = Ap[((k*Vq + vv) << 6) + w] + S[vv][w]*scl;
    }
}

// ---------------- fp16 GEMM via TMA bulk loads of packed tiles ----------------
// smem: W stages 0..3 at s*32768 (32KB each), X stages at 131072 + s*16384 (16KB),
// mbarriers at 196608. All 4 stages loaded upfront; no ring/reuse.
#define GEMM_SMEM (196608 + 64)

__global__ void __launch_bounds__(512, 1) k_gemm(const __half* __restrict__ Wh,
                                                 const __half* __restrict__ Xg,
                                                 int part) {
    extern __shared__ __align__(128) char smraw[];
    __shared__ float sred[2][256][4];
    int b  = blockIdx.z;
    int nb = blockIdx.x;
    int n0 = nb * 128;
    int tid  = threadIdx.x;
    int warp = tid >> 5, lane = tid & 31;
    int wm = warp >> 2, wn = warp & 3;           // 4 x 4 warps, warp tile 64m x 32n
    int r  = lane >> 2, c = lane & 3;
    int l16 = lane & 15, lh = lane >> 4;

    uint32_t sbase = (uint32_t)__cvta_generic_to_shared(smraw);
    uint32_t mbar  = sbase + 196608;

    if (tid == 0) {
        #pragma unroll
        for (int s = 0; s < 4; s++) MBAR_INIT(mbar + s*8, 1);
    }
    __syncthreads();
    if (tid == 0) {
        const char* wsrc = (const char*)Wh;
        const char* xsrc = (const char*)Xg + ((size_t)(b*4)*64 + nb) * 16384;
        #pragma unroll
        for (int s = 0; s < 4; s++) {
            MBAR_EXPECT_TX(mbar + s*8, 49152);
            cpbulk(sbase + s*32768,            wsrc + (size_t)s*32768,        32768, mbar + s*8);
            cpbulk(sbase + 131072 + s*16384,   xsrc + (size_t)s*64*16384,     16384, mbar + s*8);
        }
    }

    float acc[4][4][4];
    #pragma unroll
    for (int i = 0; i < 4; i++)
        #pragma unroll
        for (int j = 0; j < 4; j++)
            #pragma unroll
            for (int q = 0; q < 4; q++) acc[i][j][q] = 0.f;

    #pragma unroll
    for (int kt = 0; kt < 4; kt++) {
        MBAR_WAIT(mbar + kt*8, 0);
        uint32_t wsb = sbase + kt*32768;
        uint32_t xsb = sbase + 131072 + kt*16384;

        #pragma unroll
        for (int ks = 0; ks < 4; ks++) {
            uint32_t Af[4][4];
            #pragma unroll
            for (int mi = 0; mi < 4; mi++) {
                int m = wm*64 + mi*16 + l16;
                uint32_t a = wsb + m*128 + (((uint32_t)(ks*32 + lh*16)) ^ (((uint32_t)(m & 7)) << 4));
                ldsm_x4(Af[mi][0], Af[mi][1], Af[mi][2], Af[mi][3], a);
            }
            uint32_t Bf[2][4];
            #pragma unroll
            for (int p = 0; p < 2; p++) {
                int k = ks*16 + l16;
                int np = wn*32 + p*16 + lh*8;
                uint32_t a = xsb + k*256 + (((uint32_t)(np*2)) ^ (((uint32_t)(k & 7)) << 4));
                ldsm_x4_t(Bf[p][0], Bf[p][1], Bf[p][2], Bf[p][3], a);
            }
            #pragma unroll
            for (int mi = 0; mi < 4; mi++)
                #pragma unroll
                for (int p = 0; p < 2; p++) {
                    mma_f16(acc[mi][2*p],   Af[mi][0], Af[mi][1], Af[mi][2], Af[mi][3],
                            Bf[p][0], Bf[p][1]);
                    mma_f16(acc[mi][2*p+1], Af[mi][0], Af[mi][1], Af[mi][2], Af[mi][3],
                            Bf[p][2], Bf[p][3]);
                }
        }
    }

    // epilogue: fp16 linear store + deterministic BN partials
    __half* Yb = g_bufAh + (size_t)b*Oq*TVq;
    #pragma unroll
    for (int mi = 0; mi < 4; mi++) {
        #pragma unroll
        for (int h = 0; h < 2; h++) {
            int row = wm*64 + mi*16 + h*8 + r;
            float s = 0.f, q = 0.f;
            #pragma unroll
            for (int ni = 0; ni < 4; ni++) {
                float v0 = acc[mi][ni][2*h], v1 = acc[mi][ni][2*h + 1];
                s += v0 + v1;
                q  = fmaf(v0, v0, fmaf(v1, v1, q));
                int col = n0 + wn*32 + ni*8 + 2*c;
                *(__half2*)&Yb[(size_t)row*TVq + col] = __floats2half2_rn(v0, v1);
            }
            s += __shfl_xor_sync(0xffffffffu, s, 1);
            s += __shfl_xor_sync(0xffffffffu, s, 2);
            q += __shfl_xor_sync(0xffffffffu, q, 1);
            q += __shfl_xor_sync(0xffffffffu, q, 2);
            if (c == 0) {
                sred[0][row][wn] = s;
                sred[1][row][wn] = q;
            }
        }
    }
    __syncthreads();
    if (tid < 256) {
        int blk = blockIdx.z*64 + blockIdx.x;
        g_psum[part][blk][tid] = (sred[0][tid][0] + sred[0][tid][1])
                               + (sred[0][tid][2] + sred[0][tid][3]);
        g_psq [part][blk][tid] = (sred[1][tid][0] + sred[1][tid][1])
                               + (sred[1][tid][2] + sred[1][tid][3]);
    }
}

// deterministic reduction of BN partials -> g_stats
__global__ void k_redstats(int part) {
    int o = blockIdx.x, tid = threadIdx.x;
    float s = 0.f, q = 0.f;
    #pragma unroll
    for (int i = 0; i < 4; i++) {
        s += g_psum[part][tid + i*256][o];
        q += g_psq [part][tid + i*256][o];
    }
    __shared__ float ss[256], qq[256];
    ss[tid] = s; qq[tid] = q;
    __syncthreads();
    for (int st = 128; st > 0; st >>= 1) {
        if (tid < st) { ss[tid] += ss[tid + st]; qq[tid] += qq[tid + st]; }
        __syncthreads();
    }
    if (tid == 0) {
        g_stats[part*2*Oq + o]      = ss[0];
        g_stats[part*2*Oq + Oq + o] = qq[0];
    }
}

// ---------------- stage5 ----------------
#define HSPh 72
#define ASPh 72
#define S5H (128*HSPh + 64*ASPh)

__global__ void __launch_bounds__(256) k_stage5(const float* __restrict__ alpha_p,
                                                const float* __restrict__ gamma,
                                                const float* __restrict__ beta) {
    extern __shared__ char smraw[];
    __half* hs = (__half*)smraw;
    __half* As = hs + 128*HSPh;

    int bx = blockIdx.x;
    int b = bx >> 8, o = bx & 255, kk = o >> 5;
    int tid  = threadIdx.x;
    int warp = tid >> 5, lane = tid & 31;
    int wm = warp >> 1, wn = warp & 1;
    int r  = lane >> 2, c = lane & 3;
    int l16 = lane & 15, lh = lane >> 4;

    float mean  = g_stats[o]      * (1.f/CNT);
    float var   = g_stats[Oq + o] * (1.f/CNT) - mean*mean;
    float scale = gamma[o] * rsqrtf(var + 1e-5f);
    float shift = beta[o] - mean*scale;

    const __half* src = g_bufAh + (size_t)bx*TVq;
    for (int i = tid; i < TVq/8; i += 256) {
        int t = (i*8) >> 6, v = (i*8) & 63;
        const __half2* s2 = (const __half2*)(src + i*8);
        __half2 out[4];
        #pragma unroll
        for (int j = 0; j < 4; j++) {
            float2 f = __half22float2(s2[j]);
            out[j] = __floats2half2_rn(fmaxf(fmaf(f.x, scale, shift), 0.f),
                                       fmaxf(fmaf(f.y, scale, shift), 0.f));
        }
        *(uint2*)&hs[t*HSPh + v]     = *(uint2*)&out[0];
        *(uint2*)&hs[t*HSPh + v + 4] = *(uint2*)&out[2];
    }

    float alpha = alpha_p[0];
    const float* x1r = g_x1 + bx*Vq;
    const float* x2r = g_x2 + bx*Vq;
    const float* Mp  = g_M + (size_t)(b*Kq + kk)*Vq*Vq;
    for (int i = tid; i < Vq*Vq; i += 256) {
        int v = i >> 6, w = i & 63;
        As[v*ASPh + w] = __float2half(Mp[i] + alpha * tanhf(x1r[v] - x2r[w]));
    }
    __syncthreads();

    uint32_t hsb = (uint32_t)__cvta_generic_to_shared(hs);
    uint32_t asb = (uint32_t)__cvta_generic_to_shared(As);

    float acc[2][4][4];
    #pragma unroll
    for (int i = 0; i < 2; i++)
        #pragma unroll
        for (int j = 0; j < 4; j++)
            #pragma unroll
            for (int q = 0; q < 4; q++) acc[i][j][q] = 0.f;

    #pragma unroll
    for (int ks = 0; ks < 4; ks++) {
        uint32_t Af[2][4];
        #pragma unroll
        for (int mi = 0; mi < 2; mi++)
            ldsm_x4(Af[mi][0], Af[mi][1], Af[mi][2], Af[mi][3],
                    hsb + ((wm*32 + mi*16 + l16)*HSPh + ks*16 + 8*lh)*2);
        uint32_t Bf[2][4];
        #pragma unroll
        for (int p = 0; p < 2; p++)
            ldsm_x4_t(Bf[p][0], Bf[p][1], Bf[p][2], Bf[p][3],
                      asb + ((ks*16 + l16)*ASPh + wn*32 + p*16 + 8*lh)*2);
        #pragma unroll
        for (int mi = 0; mi < 2; mi++)
            #pragma unroll
            for (int p = 0; p < 2; p++) {
                mma_f16(acc[mi][2*p],   Af[mi][0], Af[mi][1], Af[mi][2], Af[mi][3],
                        Bf[p][0], Bf[p][1]);
                mma_f16(acc[mi][2*p+1], Af[mi][0], Af[mi][1], Af[mi][2], Af[mi][3],
                        Bf[p][2], Bf[p][3]);
            }
    }

    // write packed+swizzled for head-GEMM TMA: s = o>>6, kr = o&63
    {
        int s = o >> 6, kr = o & 63;
        int swz = (kr & 7) << 3;
        __half* dstb = g_bufBh + ((size_t)(b*4 + s)*64) * 8192 + (size_t)kr*128;
        #pragma unroll
        for (int mi = 0; mi < 2; mi++) {
            #pragma unroll
            for (int h = 0; h < 2; h++) {
                int t = wm*32 + mi*16 + h*8 + r;
                int nb = t >> 1;
                #pragma unroll
                for (int ni = 0; ni < 4; ni++) {
                    int w = wn*32 + ni*8 + 2*c;
                    int nc = (t & 1)*64 + w;
                    size_t hoff = (size_t)nb*8192 + (nc ^ swz);
                    *(__half2*)&dstb[hoff] = __floats2half2_rn(acc[mi][ni][2*h], acc[mi][ni][2*h+1]);
                }
            }
        }
    }
}

// out = relu(BN(z) + x); z linear fp16, residual x from PACKED g_xh
__global__ void k_out(const float* __restrict__ gamma, const float* __restrict__ beta,
                      float* __restrict__ out) {
    size_t base = (size_t)blockIdx.x * 1024 + threadIdx.x;
    const __half2* zph = (const __half2*)(g_bufAh);

    __half2 z[4][2], xv[4][2];
    #pragma unroll
    for (int j = 0; j < 4; j++) {
        size_t i4 = base + j*256;
        z[j][0] = zph[i4*2];  z[j][1] = zph[i4*2 + 1];
        size_t e = i4*4;
        int bb = (int)(e >> 21);
        int cc = (int)((e >> 13) & 255);
        int tv = (int)(e & 8191);
        int s = cc >> 6, kr = cc & 63;
        int nb = tv >> 7, nc = tv & 127;
        size_t hoff = ((size_t)(bb*4 + s)*64 + nb)*8192 + kr*128 + (nc ^ ((kr & 7) << 3));
        uint2 u = *(const uint2*)&g_xh[hoff];
        xv[j][0] = *(__half2*)&u.x;
        xv[j][1] = *(__half2*)&u.y;
    }
    #pragma unroll
    for (int j = 0; j < 4; j++) {
        size_t i4 = base + j*256;
        int o = (int)((i4 >> 11) & 255);
        float mean  = g_stats[2*Oq + o] * (1.f/CNT);
        float var   = g_stats[3*Oq + o] * (1.f/CNT) - mean*mean;
        float scale = gamma[o] * rsqrtf(var + 1e-5f);
        float shift = beta[o] - mean*scale;
        float2 z0 = __half22float2(z[j][0]);
        float2 z1 = __half22float2(z[j][1]);
        float2 x0 = __half22float2(xv[j][0]);
        float2 x1 = __half22float2(xv[j][1]);
        float4 rr;
        rr.x = fmaxf(fmaf(z0.x, scale, shift) + x0.x, 0.f);
        rr.y = fmaxf(fmaf(z0.y, scale, shift) + x0.y, 0.f);
        rr.z = fmaxf(fmaf(z1.x, scale, shift) + x1.x, 0.f);
        rr.w = fmaxf(fmaf(z1.y, scale, shift) + x1.y, 0.f);
        ((float4*)out)[i4] = rr;
    }
}

// ---------------- launch ----------------
extern "C" void kernel_launch(void* const* d_in, const int* in_sizes, int n_in,
                              void* d_out, int out_size) {
    const float* x       = (const float*)d_in[0];
    const float* A_param = (const float*)d_in[1];
    const float* alpha   = (const float*)d_in[2];
    const float* beta    = (const float*)d_in[3];
    const float* w1      = (const float*)d_in[4];
    const float* b1      = (const float*)d_in[5];
    const float* w2      = (const float*)d_in[6];
    const float* b2      = (const float*)d_in[7];
    const float* stem_w  = (const float*)d_in[8];
    const float* stem_g  = (const float*)d_in[10];
    const float* stem_be = (const float*)d_in[11];
    const float* head_w  = (const float*)d_in[12];
    const float* head_g  = (const float*)d_in[14];
    const float* head_be = (const float*)d_in[15];
    float* out = (float*)d_out;

    int stage5_smem = S5H * 2;
    cudaFuncSetAttribute(k_gemm,   cudaFuncAttributeMaxDynamicSharedMemorySize, GEMM_SMEM);
    cudaFuncSetAttribute(k_stage5, cudaFuncAttributeMaxDynamicSharedMemorySize, stage5_smem);

    __half* whp = nullptr;  cudaGetSymbolAddress((void**)&whp, g_wh);
    __half* xhp = nullptr;  cudaGetSymbolAddress((void**)&xhp, g_xh);
    __half* bBp = nullptr;  cudaGetSymbolAddress((void**)&bBp, g_bufBh);

    k_meanT<<<Bq*Cq + 256, 256>>>(x, stem_w, head_w);
    k_x1x2<<<dim3(Oq/16, Bq), 256>>>(w1, b1, w2, b2);
    k_adj<<<Bq*Kq, 256>>>(A_param, beta);

    // stem conv + deterministic BN partials (bias cancels in BN)
    k_gemm<<<dim3(TVq/128, 1, Bq), 512, GEMM_SMEM>>>(whp, xhp, 0);
    k_redstats<<<Oq, 256>>>(0);

    // BN+relu + graph matmul (writes packed X for head GEMM)
    k_stage5<<<Bq*Oq, 256, stage5_smem>>>(alpha, stem_g, stem_be);

    // head conv + deterministic BN partials
    k_gemm<<<dim3(TVq/128, 1, Bq), 512, GEMM_SMEM>>>(whp + Oq*Cq, bBp, 1);
    k_redstats<<<Oq, 256>>>(1);

    k_out<<<(int)(((size_t)Bq*Oq*TVq/4)/1024), 256>>>(head_g, head_be, out);
}